// round 6
// baseline (speedup 1.0000x reference)
#include <cuda_runtime.h>
#include <math.h>
#include <stdint.h>

// ---------------- problem constants ----------------
#define LSEQ   2048
#define DMODEL 1024
#define DINNER 2048
#define DSTATE 16
#define DTRANK 64
#define XDBL   96
#define NEXP   8
#define HIDDEN 4096
#define NPAIR  4096
#define SPLITK 8

// ---------------- fp32 scratch ----------------
__device__ float g_xn   [LSEQ * DMODEL];
__device__ float g_xr   [LSEQ * 2 * DINNER];
__device__ float g_u    [LSEQ * DINNER];
__device__ float g_xdbl [LSEQ * XDBL];
__device__ float g_xp   [SPLITK * LSEQ * XDBL];
__device__ float g_delta[LSEQ * DINNER];
__device__ float g_y    [LSEQ * DINNER];
__device__ float g_xm2  [LSEQ * DMODEL];
__device__ float g_xm2n [LSEQ * DMODEL];
__device__ float g_hf   [(size_t)NPAIR * HIDDEN];   // 64 MB
__device__ float g_y2   [(size_t)NPAIR * DMODEL];
__device__ int   g_top_e[LSEQ * 2];
__device__ float g_top_v[LSEQ * 2];
__device__ int   g_cnt[NEXP];
__device__ int   g_cur[NEXP];
__device__ int   g_off[NEXP + 1];
__device__ int   g_ptok[NPAIR];
__device__ float g_pw  [NPAIR];
__device__ int   g_tok_pair[LSEQ * 2];

// ---------------- int8 hi/lo scratch + row scales ----------------
__device__ __align__(16) int8_t q_xn_h[LSEQ * DMODEL], q_xn_l[LSEQ * DMODEL];
__device__ __align__(16) int8_t q_xd_h[LSEQ * DTRANK], q_xd_l[LSEQ * DTRANK];
__device__ __align__(16) int8_t q_y_h [LSEQ * DINNER], q_y_l [LSEQ * DINNER];
__device__ __align__(16) int8_t q_x2_h[LSEQ * DMODEL], q_x2_l[LSEQ * DMODEL];
__device__ __align__(16) int8_t q_h_h [(size_t)NPAIR * HIDDEN], q_h_l [(size_t)NPAIR * HIDDEN];
__device__ __align__(16) int8_t q_wi_h[2 * DINNER * DMODEL], q_wi_l[2 * DINNER * DMODEL];
__device__ __align__(16) int8_t q_wd_h[DINNER * DTRANK],     q_wd_l[DINNER * DTRANK];
__device__ __align__(16) int8_t q_wo_h[DMODEL * DINNER],     q_wo_l[DMODEL * DINNER];
__device__ __align__(16) int8_t q_w1_h[(size_t)NEXP * HIDDEN * DMODEL], q_w1_l[(size_t)NEXP * HIDDEN * DMODEL];
__device__ __align__(16) int8_t q_w2_h[(size_t)NEXP * DMODEL * HIDDEN], q_w2_l[(size_t)NEXP * DMODEL * HIDDEN];
__device__ float s_xn[LSEQ], s_xd[LSEQ], s_y[LSEQ], s_x2[LSEQ], s_h[NPAIR];
__device__ float s_wi[2 * DINNER], s_wd[DINNER], s_wo[DMODEL];
__device__ float s_w1[NEXP * HIDDEN], s_w2[NEXP * DMODEL];

// ---------------- helpers ----------------
__device__ __forceinline__ void cpa16(uint32_t dst, const void* src)
{
    asm volatile("cp.async.cg.shared.global [%0], [%1], 16;" :: "r"(dst), "l"(src));
}

__device__ __forceinline__ void imma(int* d, const uint32_t* a, const uint32_t* b)
{
    asm volatile(
        "mma.sync.aligned.m16n8k32.row.col.s32.s8.s8.s32 "
        "{%0,%1,%2,%3},{%4,%5,%6,%7},{%8,%9},{%0,%1,%2,%3};\n"
        : "+r"(d[0]), "+r"(d[1]), "+r"(d[2]), "+r"(d[3])
        : "r"(a[0]), "r"(a[1]), "r"(a[2]), "r"(a[3]), "r"(b[0]), "r"(b[1]));
}

// fragment load from swizzled tile: rows of 64B = 16 words, quarter swizzle
__device__ __forceinline__ uint32_t fr(const uint32_t* s, int row, int w)
{
    return s[row * 16 + ((((w >> 2) ^ ((row >> 1) & 3)) << 2) | (w & 3))];
}

// ---------------- generic row quantizer: x ~ s*(qh*256+ql) ----------------
__global__ void quant_rows(const float* __restrict__ src, int lda, int K,
                           int8_t* __restrict__ qh, int8_t* __restrict__ ql,
                           float* __restrict__ sc)
{
    int row = blockIdx.x;
    const float4* p = (const float4*)(src + (size_t)row * lda);
    int K4 = K >> 2;
    float mx = 0.f;
    for (int k = threadIdx.x; k < K4; k += 128) {
        float4 v = p[k];
        mx = fmaxf(mx, fmaxf(fmaxf(fabsf(v.x), fabsf(v.y)), fmaxf(fabsf(v.z), fabsf(v.w))));
    }
    __shared__ float sh[4];
    #pragma unroll
    for (int o = 16; o; o >>= 1) mx = fmaxf(mx, __shfl_xor_sync(0xffffffffu, mx, o));
    if ((threadIdx.x & 31) == 0) sh[threadIdx.x >> 5] = mx;
    __syncthreads();
    mx = fmaxf(fmaxf(sh[0], sh[1]), fmaxf(sh[2], sh[3]));
    mx = fmaxf(mx, 1e-20f);
    float invs = 32256.f / mx;
    if (threadIdx.x == 0) sc[row] = mx * (1.f / 32256.f);
    char4* qhp = (char4*)(qh + (size_t)row * K);
    char4* qlp = (char4*)(ql + (size_t)row * K);
    for (int k = threadIdx.x; k < K4; k += 128) {
        float4 v = p[k];
        int i0 = __float2int_rn(v.x * invs), i1 = __float2int_rn(v.y * invs);
        int i2 = __float2int_rn(v.z * invs), i3 = __float2int_rn(v.w * invs);
        int h0 = (i0 + 128) >> 8, h1 = (i1 + 128) >> 8;
        int h2 = (i2 + 128) >> 8, h3 = (i3 + 128) >> 8;
        qhp[k] = make_char4((char)h0, (char)h1, (char)h2, (char)h3);
        qlp[k] = make_char4((char)(i0 - (h0 << 8)), (char)(i1 - (h1 << 8)),
                            (char)(i2 - (h2 << 8)), (char)(i3 - (h3 << 8)));
    }
}

// ---------------- int8 fixed-point tensor GEMM: C = epi(A @ W^T) ----------------
// A: (M,K) int8 hi/lo rows + scale sa[row]; W: (N,K) int8 hi/lo + scale sb[n].
// CTA tile 128m x 64n, k-stage 64, cp.async double buffered. 256 threads,
// 8 warps as 2m x 4n (warp tile 64x16).
// EPI: 0 store fp32, 1 gelu->fp32, 2 +addsrc fp32, 3 softplus(+bias)
// MODE: 0 plain, 1 gather A rows via ptok + per-expert W, 2 contiguous expert rows
#define STG_B 24576
template<int EPI, int MODE>
__global__ void __launch_bounds__(256, 2) igemm(
    const int8_t* __restrict__ Ahi, const int8_t* __restrict__ Alo,
    const float* __restrict__ sa, int lda,
    const int8_t* __restrict__ Whi, const int8_t* __restrict__ Wlo,
    const float* __restrict__ sbsc, int K,
    float* __restrict__ C, int ldc, int M, int N,
    const float* __restrict__ bias, const float* __restrict__ addsrc, int ldadd,
    const int* __restrict__ off, const int* __restrict__ ptok)
{
    extern __shared__ __align__(16) uint8_t smem[];
    int base = 0, rows = M;
    const int8_t *Wh = Whi, *Wl = Wlo;
    const float* sb = sbsc;
    if (MODE != 0) {
        int e = blockIdx.z;
        base = off[e];
        rows = off[e + 1] - base;
        Wh += (size_t)e * (size_t)N * K;
        Wl += (size_t)e * (size_t)N * K;
        sb += (size_t)e * N;
    }
    int m0 = blockIdx.x * 128;
    if (m0 >= rows) return;
    int n0 = blockIdx.y * 64;

    int tid = threadIdx.x;
    int wid = tid >> 5, lane = tid & 31;
    int lr = lane >> 2, lc = lane & 3;
    int warp_m = wid >> 2, warp_n = wid & 3;

    int qg = tid & 3;
    int ar = tid >> 2;                 // 0..63

    // A global rows (clamped; masked in epilogue)
    int rA0 = m0 + ar, rA1 = m0 + ar + 64;
    int c0 = rA0 < rows ? rA0 : rows - 1;
    int c1 = rA1 < rows ? rA1 : rows - 1;
    int gA0, gA1;
    if (MODE == 1)      { gA0 = ptok[base + c0]; gA1 = ptok[base + c1]; }
    else if (MODE == 2) { gA0 = base + c0;       gA1 = base + c1; }
    else                { gA0 = c0;              gA1 = c1; }

    const int8_t* pAh0 = Ahi + (size_t)gA0 * lda + qg * 16;
    const int8_t* pAh1 = Ahi + (size_t)gA1 * lda + qg * 16;
    const int8_t* pAl0 = Alo + (size_t)gA0 * lda + qg * 16;
    const int8_t* pAl1 = Alo + (size_t)gA1 * lda + qg * 16;
    const int8_t* pBh  = Wh + (size_t)(n0 + ar) * K + qg * 16;
    const int8_t* pBl  = Wl + (size_t)(n0 + ar) * K + qg * 16;

    uint32_t sb0 = (uint32_t)__cvta_generic_to_shared(smem);
    int seg = (qg ^ ((ar >> 1) & 3)) * 16;
    int dA0 = ar * 64 + seg;
    int dA1 = dA0 + 64 * 64;
    int dB  = ar * 64 + seg;

    int hh[4][2][4], md[4][2][4];
    #pragma unroll
    for (int i = 0; i < 4; i++)
        #pragma unroll
        for (int j = 0; j < 2; j++)
            #pragma unroll
            for (int r = 0; r < 4; r++) { hh[i][j][r] = 0; md[i][j][r] = 0; }

    int nt = K >> 6;
    // prologue: stage 0
    {
        cpa16(sb0 + 0     + dA0, pAh0);
        cpa16(sb0 + 0     + dA1, pAh1);
        cpa16(sb0 + 8192  + dA0, pAl0);
        cpa16(sb0 + 8192  + dA1, pAl1);
        cpa16(sb0 + 16384 + dB,  pBh);
        cpa16(sb0 + 20480 + dB,  pBl);
        asm volatile("cp.async.commit_group;");
    }
    for (int t = 0; t < nt; t++) {
        __syncthreads();
        if (t + 1 < nt) {
            int kc = (t + 1) << 6;
            uint32_t s = sb0 + ((t + 1) & 1) * STG_B;
            cpa16(s + 0     + dA0, pAh0 + kc);
            cpa16(s + 0     + dA1, pAh1 + kc);
            cpa16(s + 8192  + dA0, pAl0 + kc);
            cpa16(s + 8192  + dA1, pAl1 + kc);
            cpa16(s + 16384 + dB,  pBh + kc);
            cpa16(s + 20480 + dB,  pBl + kc);
        }
        asm volatile("cp.async.commit_group;");
        asm volatile("cp.async.wait_group 1;");
        __syncthreads();

        const uint32_t* S = (const uint32_t*)(smem + (t & 1) * STG_B);
        const uint32_t* sAh = S;
        const uint32_t* sAl = S + 2048;
        const uint32_t* sBh = S + 4096;
        const uint32_t* sBl = S + 5120;

        #pragma unroll
        for (int sub = 0; sub < 2; sub++) {
            int w0 = sub * 8 + lc, w1 = w0 + 4;
            uint32_t bh[2][2], bl[2][2];
            #pragma unroll
            for (int in = 0; in < 2; in++) {
                int n = warp_n * 16 + in * 8 + lr;
                bh[in][0] = fr(sBh, n, w0); bh[in][1] = fr(sBh, n, w1);
                bl[in][0] = fr(sBl, n, w0); bl[in][1] = fr(sBl, n, w1);
            }
            #pragma unroll
            for (int im = 0; im < 4; im++) {
                int m = warp_m * 64 + im * 16 + lr;
                uint32_t ah[4] = { fr(sAh, m, w0), fr(sAh, m + 8, w0),
                                   fr(sAh, m, w1), fr(sAh, m + 8, w1) };
                uint32_t al[4] = { fr(sAl, m, w0), fr(sAl, m + 8, w0),
                                   fr(sAl, m, w1), fr(sAl, m + 8, w1) };
                #pragma unroll
                for (int in = 0; in < 2; in++) {
                    imma(hh[im][in], ah, bh[in]);
                    imma(md[im][in], ah, bl[in]);
                    imma(md[im][in], al, bh[in]);
                }
            }
        }
    }

    // epilogue
    #pragma unroll
    for (int im = 0; im < 4; im++) {
        #pragma unroll
        for (int half = 0; half < 2; half++) {
            int ml = warp_m * 64 + im * 16 + lr + half * 8;
            int m = m0 + ml;
            if (m >= rows) continue;
            float sam;
            size_t crow;
            if (MODE == 1)      { int tok = ptok[base + m]; sam = sa[tok]; crow = (size_t)(base + m) * ldc; }
            else if (MODE == 2) { sam = sa[base + m]; crow = (size_t)(base + m) * ldc; }
            else                { sam = sa[m]; crow = (size_t)m * ldc; }
            #pragma unroll
            for (int in = 0; in < 2; in++) {
                int n = n0 + warp_n * 16 + in * 8 + lc * 2;
                float r0 = fmaf(65536.f, (float)hh[im][in][half * 2],     256.f * (float)md[im][in][half * 2]);
                float r1 = fmaf(65536.f, (float)hh[im][in][half * 2 + 1], 256.f * (float)md[im][in][half * 2 + 1]);
                float v0 = sam * sb[n] * r0;
                float v1 = sam * sb[n + 1] * r1;
                if (EPI == 1) {
                    v0 = 0.5f * v0 * (1.0f + erff(v0 * 0.70710678118654752f));
                    v1 = 0.5f * v1 * (1.0f + erff(v1 * 0.70710678118654752f));
                } else if (EPI == 2) {
                    v0 += addsrc[(size_t)m * ldadd + n];
                    v1 += addsrc[(size_t)m * ldadd + n + 1];
                } else if (EPI == 3) {
                    float z0 = v0 + bias[n], z1 = v1 + bias[n + 1];
                    v0 = (z0 > 20.f) ? z0 : log1pf(__expf(z0));
                    v1 = (z1 > 20.f) ? z1 : log1pf(__expf(z1));
                }
                *(float2*)(C + crow + n) = make_float2(v0, v1);
            }
        }
    }
}

// ---------------- rmsnorm (writes fp32 + int8 hi/lo + scale) ----------------
__global__ void rmsnorm_q(const float* __restrict__ x, float* __restrict__ o,
                          int8_t* __restrict__ qh, int8_t* __restrict__ ql,
                          float* __restrict__ sc)
{
    int row = blockIdx.x;
    const float4* xp = (const float4*)(x + (size_t)row * DMODEL);
    float4 v = xp[threadIdx.x];                       // 256 thr x 4 = 1024
    float s = v.x * v.x + v.y * v.y + v.z * v.z + v.w * v.w;
    float mx = fmaxf(fmaxf(fabsf(v.x), fabsf(v.y)), fmaxf(fabsf(v.z), fabsf(v.w)));
    __shared__ float ssum[8], smax[8], bc[2];
    #pragma unroll
    for (int off = 16; off; off >>= 1) {
        s += __shfl_xor_sync(0xffffffffu, s, off);
        mx = fmaxf(mx, __shfl_xor_sync(0xffffffffu, mx, off));
    }
    if ((threadIdx.x & 31) == 0) { ssum[threadIdx.x >> 5] = s; smax[threadIdx.x >> 5] = mx; }
    __syncthreads();
    if (threadIdx.x == 0) {
        float ts = 0.f, tm = 0.f;
        #pragma unroll
        for (int i = 0; i < 8; i++) { ts += ssum[i]; tm = fmaxf(tm, smax[i]); }
        bc[0] = ts; bc[1] = tm;
    }
    __syncthreads();
    float scale = 32.0f / fmaxf(sqrtf(bc[0]), 1e-12f);
    float mxv = fmaxf(bc[1] * scale, 1e-20f);
    float invs = 32256.f / mxv;
    if (threadIdx.x == 0) sc[row] = mxv * (1.f / 32256.f);
    float4 w = make_float4(v.x * scale, v.y * scale, v.z * scale, v.w * scale);
    ((float4*)(o + (size_t)row * DMODEL))[threadIdx.x] = w;
    int i0 = __float2int_rn(w.x * invs), i1 = __float2int_rn(w.y * invs);
    int i2 = __float2int_rn(w.z * invs), i3 = __float2int_rn(w.w * invs);
    int h0 = (i0 + 128) >> 8, h1 = (i1 + 128) >> 8, h2 = (i2 + 128) >> 8, h3 = (i3 + 128) >> 8;
    ((char4*)(qh + (size_t)row * DMODEL))[threadIdx.x] =
        make_char4((char)h0, (char)h1, (char)h2, (char)h3);
    ((char4*)(ql + (size_t)row * DMODEL))[threadIdx.x] =
        make_char4((char)(i0 - (h0 << 8)), (char)(i1 - (h1 << 8)),
                   (char)(i2 - (h2 << 8)), (char)(i3 - (h3 << 8)));
}

// ---------------- split-K SIMT GEMM for skinny x_proj (exact fp32) ----------------
__global__ void __launch_bounds__(256) gemm_sk(
    const float* __restrict__ A, int lda,
    const float* __restrict__ W, int ldw,
    float* __restrict__ Cpart, int ldc,
    int M, int N, int kchunk)
{
    int koff = blockIdx.z * kchunk;
    float* C = Cpart + (size_t)blockIdx.z * M * ldc;
    __shared__ float As[16][68];
    __shared__ float Bs[16][68];
    int tid = threadIdx.x;
    int m0 = blockIdx.x * 64, n0 = blockIdx.y * 64;
    int tx = tid & 15, ty = tid >> 4;
    int lr = tid >> 2;
    int lk = (tid & 3) << 2;
    int am = m0 + lr;
    int wn = n0 + lr;
    bool a_ok = am < M;
    bool w_ok = wn < N;
    const float* Arow = A + (size_t)(a_ok ? am : 0) * lda + koff;
    const float* Wrow = W + (size_t)(w_ok ? wn : 0) * ldw + koff;
    float acc[4][4] = {};
    for (int k0 = 0; k0 < kchunk; k0 += 16) {
        float4 av = a_ok ? *(const float4*)(Arow + k0 + lk) : make_float4(0, 0, 0, 0);
        float4 wv = w_ok ? *(const float4*)(Wrow + k0 + lk) : make_float4(0, 0, 0, 0);
        __syncthreads();
        As[lk][lr] = av.x; As[lk + 1][lr] = av.y; As[lk + 2][lr] = av.z; As[lk + 3][lr] = av.w;
        Bs[lk][lr] = wv.x; Bs[lk + 1][lr] = wv.y; Bs[lk + 2][lr] = wv.z; Bs[lk + 3][lr] = wv.w;
        __syncthreads();
        #pragma unroll
        for (int k = 0; k < 16; k++) {
            float a[4], b[4];
            #pragma unroll
            for (int i = 0; i < 4; i++) a[i] = As[k][ty * 4 + i];
            #pragma unroll
            for (int j = 0; j < 4; j++) b[j] = Bs[k][tx * 4 + j];
            #pragma unroll
            for (int i = 0; i < 4; i++)
                #pragma unroll
                for (int j = 0; j < 4; j++)
                    acc[i][j] += a[i] * b[j];
        }
    }
    #pragma unroll
    for (int i = 0; i < 4; i++) {
        int m = m0 + ty * 4 + i;
        if (m >= M) continue;
        #pragma unroll
        for (int j = 0; j < 4; j++) {
            int n = n0 + tx * 4 + j;
            if (n >= N) continue;
            C[(size_t)m * ldc + n] = acc[i][j];
        }
    }
}

__global__ void reduce_sk(const float* __restrict__ p, float* __restrict__ o, int n)
{
    int i = blockIdx.x * 256 + threadIdx.x;
    if (i >= n) return;
    float s = 0.f;
    #pragma unroll
    for (int j = 0; j < SPLITK; j++) s += p[i + (size_t)j * n];
    o[i] = s;
}

// ---------------- causal depthwise conv(4) + silu ----------------
__global__ void conv_silu(const float* __restrict__ xr, const float* __restrict__ cw,
                          const float* __restrict__ cb, float* __restrict__ u)
{
    int idx = blockIdx.x * 256 + threadIdx.x;
    int t = idx >> 11, d = idx & (DINNER - 1);
    float w0 = cw[d * 4], w1 = cw[d * 4 + 1], w2 = cw[d * 4 + 2], w3 = cw[d * 4 + 3];
    float s = cb[d];
    const float* col = xr + d;
    if (t >= 3) s += col[(size_t)(t - 3) * (2 * DINNER)] * w0;
    if (t >= 2) s += col[(size_t)(t - 2) * (2 * DINNER)] * w1;
    if (t >= 1) s += col[(size_t)(t - 1) * (2 * DINNER)] * w2;
    s += col[(size_t)t * (2 * DINNER)] * w3;
    u[idx] = s / (1.f + __expf(-s));
}

// ---------------- selective scan (fp32 y out) ----------------
__global__ void scan_kernel(const float* __restrict__ delta,
                            const float* __restrict__ u,
                            const float* __restrict__ xdbl,
                            const float* __restrict__ A_log,
                            const float* __restrict__ Dvec,
                            const float* __restrict__ xr,
                            float* __restrict__ y)
{
    int lane16 = threadIdx.x & 15;
    int ch = threadIdx.x >> 4;
    int d = blockIdx.x * 8 + ch;
    float A = -__expf(A_log[d * DSTATE + lane16]);
    float Dd = Dvec[d];
    float h = 0.f;
    __shared__ float sB[32][16], sC[32][16], sdl[32][8], su[32][8], sre[32][8];
    for (int t0 = 0; t0 < LSEQ; t0 += 32) {
        __syncthreads();
        for (int i = threadIdx.x; i < 512; i += 128) {
            int tt = i >> 4, n = i & 15;
            const float* xb = xdbl + (size_t)(t0 + tt) * XDBL;
            sB[tt][n] = xb[DTRANK + n];
            sC[tt][n] = xb[DTRANK + DSTATE + n];
        }
        for (int i = threadIdx.x; i < 256; i += 128) {
            int tt = i >> 3, c = i & 7;
            int dd = blockIdx.x * 8 + c;
            size_t off = (size_t)(t0 + tt) * DINNER + dd;
            sdl[tt][c] = delta[off];
            su[tt][c]  = u[off];
            sre[tt][c] = xr[(size_t)(t0 + tt) * (2 * DINNER) + DINNER + dd];
        }
        __syncthreads();
        for (int tt = 0; tt < 32; tt++) {
            float dl = sdl[tt][ch];
            float uu = su[tt][ch];
            float dA = __expf(dl * A);
            h = dA * h + dl * sB[tt][lane16] * uu;
            float p = h * sC[tt][lane16];
            #pragma unroll
            for (int o = 8; o; o >>= 1) p += __shfl_xor_sync(0xffffffffu, p, o, 16);
            if (lane16 == 0) {
                float yv = p + uu * Dd;
                float r = sre[tt][ch];
                yv *= r / (1.f + __expf(-r));
                y[(size_t)(t0 + tt) * DINNER + d] = yv;
            }
        }
    }
}

// ---------------- gating: GEMV + softmax + top-2 ----------------
__global__ void gate_topk(const float* __restrict__ X, const float* __restrict__ gw,
                          int* __restrict__ te, float* __restrict__ tv)
{
    __shared__ float sg[NEXP * DMODEL];
    for (int i = threadIdx.x; i < NEXP * DMODEL; i += 128) sg[i] = gw[i];
    __syncthreads();
    int warp = threadIdx.x >> 5, lane = threadIdx.x & 31;
    int t = blockIdx.x * 4 + warp;
    const float* xp = X + (size_t)t * DMODEL;
    float acc[NEXP] = {};
    for (int k = lane; k < DMODEL; k += 32) {
        float xv = xp[k];
        #pragma unroll
        for (int e = 0; e < NEXP; e++) acc[e] += xv * sg[e * DMODEL + k];
    }
    #pragma unroll
    for (int e = 0; e < NEXP; e++)
        #pragma unroll
        for (int o = 16; o; o >>= 1) acc[e] += __shfl_xor_sync(0xffffffffu, acc[e], o);
    if (lane == 0) {
        float m = acc[0];
        #pragma unroll
        for (int e = 1; e < NEXP; e++) m = fmaxf(m, acc[e]);
        float g[NEXP];
        #pragma unroll
        for (int e = 0; e < NEXP; e++) g[e] = __expf(acc[e] - m);
        int i0 = 0;
        #pragma unroll
        for (int e = 1; e < NEXP; e++) if (g[e] > g[i0]) i0 = e;
        int i1 = (i0 == 0) ? 1 : 0;
        #pragma unroll
        for (int e = 0; e < NEXP; e++) if (e != i0 && g[e] > g[i1]) i1 = e;
        float inv = 1.f / (g[i0] + g[i1]);
        te[t * 2] = i0; te[t * 2 + 1] = i1;
        tv[t * 2] = g[i0] * inv; tv[t * 2 + 1] = g[i1] * inv;
    }
}

// ---------------- routing ----------------
__global__ void route_zero(int* cnt, int* cur)
{
    if (threadIdx.x < NEXP) { cnt[threadIdx.x] = 0; cur[threadIdx.x] = 0; }
}
__global__ void route_count(const int* __restrict__ te, int* cnt)
{
    int t = blockIdx.x * 256 + threadIdx.x;
    atomicAdd(&cnt[te[t * 2]], 1);
    atomicAdd(&cnt[te[t * 2 + 1]], 1);
}
__global__ void route_offsets(const int* __restrict__ cnt, int* off)
{
    int s = 0;
    for (int e = 0; e < NEXP; e++) { off[e] = s; s += cnt[e]; }
    off[NEXP] = s;
}
__global__ void route_scatter(const int* __restrict__ te, const float* __restrict__ tv,
                              const int* __restrict__ off, int* cur,
                              int* ptok, float* pw, int* tok_pair)
{
    int t = blockIdx.x * 256 + threadIdx.x;
    #pragma unroll
    for (int k = 0; k < 2; k++) {
        int e = te[t * 2 + k];
        int pos = atomicAdd(&cur[e], 1);
        int p = off[e] + pos;
        ptok[p] = t;
        pw[p] = tv[t * 2 + k];
        tok_pair[t * 2 + k] = p;
    }
}

// ---------------- final combine ----------------
__global__ void moe_combine(const float* __restrict__ x, const float* __restrict__ y2,
                            const int* __restrict__ tok_pair, const float* __restrict__ pw,
                            float* __restrict__ out)
{
    int i = blockIdx.x * 256 + threadIdx.x;
    int t = i >> 10, n = i & (DMODEL - 1);
    int p0 = tok_pair[t * 2], p1 = tok_pair[t * 2 + 1];
    out[i] = x[i] + pw[p0] * y2[(size_t)p0 * DMODEL + n]
                  + pw[p1] * y2[(size_t)p1 * DMODEL + n];
}

// ---------------- launch ----------------
extern "C" void kernel_launch(void* const* d_in, const int* in_sizes, int n_in,
                              void* d_out, int out_size)
{
    (void)in_sizes; (void)n_in; (void)out_size;
    const float* x          = (const float*)d_in[0];
    const float* in_proj_w  = (const float*)d_in[1];
    const float* conv_w     = (const float*)d_in[2];
    const float* conv_b     = (const float*)d_in[3];
    const float* x_proj_w   = (const float*)d_in[4];
    const float* dt_proj_w  = (const float*)d_in[5];
    const float* dt_proj_b  = (const float*)d_in[6];
    const float* A_log      = (const float*)d_in[7];
    const float* Dvec       = (const float*)d_in[8];
    const float* out_proj_w = (const float*)d_in[9];
    const float* gate_w     = (const float*)d_in[10];
    const float* w1         = (const float*)d_in[11];
    const float* w2         = (const float*)d_in[12];
    float* out = (float*)d_out;

    float *p_xn, *p_xr, *p_u, *p_xdbl, *p_xp, *p_delta, *p_y, *p_xm2, *p_xm2n, *p_hf, *p_y2, *p_tv, *p_pw;
    int *p_te, *p_cnt, *p_cur, *p_off, *p_ptok, *p_tp;
    cudaGetSymbolAddress((void**)&p_xn, g_xn);
    cudaGetSymbolAddress((void**)&p_xr, g_xr);
    cudaGetSymbolAddress((void**)&p_u, g_u);
    cudaGetSymbolAddress((void**)&p_xdbl, g_xdbl);
    cudaGetSymbolAddress((void**)&p_xp, g_xp);
    cudaGetSymbolAddress((void**)&p_delta, g_delta);
    cudaGetSymbolAddress((void**)&p_y, g_y);
    cudaGetSymbolAddress((void**)&p_xm2, g_xm2);
    cudaGetSymbolAddress((void**)&p_xm2n, g_xm2n);
    cudaGetSymbolAddress((void**)&p_hf, g_hf);
    cudaGetSymbolAddress((void**)&p_y2, g_y2);
    cudaGetSymbolAddress((void**)&p_te, g_top_e);
    cudaGetSymbolAddress((void**)&p_tv, g_top_v);
    cudaGetSymbolAddress((void**)&p_cnt, g_cnt);
    cudaGetSymbolAddress((void**)&p_cur, g_cur);
    cudaGetSymbolAddress((void**)&p_off, g_off);
    cudaGetSymbolAddress((void**)&p_ptok, g_ptok);
    cudaGetSymbolAddress((void**)&p_pw, g_pw);
    cudaGetSymbolAddress((void**)&p_tp, g_tok_pair);

    int8_t *xnh, *xnl, *xdh, *xdl, *yh, *yl, *x2h, *x2l, *hh, *hl;
    int8_t *wih, *wil, *wdh, *wdl, *woh, *wol, *w1h, *w1l, *w2h, *w2l;
    float *sxn, *sxd, *sy, *sx2, *shh, *swi, *swd, *swo, *sw1, *sw2;
    cudaGetSymbolAddress((void**)&xnh, q_xn_h); cudaGetSymbolAddress((void**)&xnl, q_xn_l);
    cudaGetSymbolAddress((void**)&xdh, q_xd_h); cudaGetSymbolAddress((void**)&xdl, q_xd_l);
    cudaGetSymbolAddress((void**)&yh,  q_y_h);  cudaGetSymbolAddress((void**)&yl,  q_y_l);
    cudaGetSymbolAddress((void**)&x2h, q_x2_h); cudaGetSymbolAddress((void**)&x2l, q_x2_l);
    cudaGetSymbolAddress((void**)&hh,  q_h_h);  cudaGetSymbolAddress((void**)&hl,  q_h_l);
    cudaGetSymbolAddress((void**)&wih, q_wi_h); cudaGetSymbolAddress((void**)&wil, q_wi_l);
    cudaGetSymbolAddress((void**)&wdh, q_wd_h); cudaGetSymbolAddress((void**)&wdl, q_wd_l);
    cudaGetSymbolAddress((void**)&woh, q_wo_h); cudaGetSymbolAddress((void**)&wol, q_wo_l);
    cudaGetSymbolAddress((void**)&w1h, q_w1_h); cudaGetSymbolAddress((void**)&w1l, q_w1_l);
    cudaGetSymbolAddress((void**)&w2h, q_w2_h); cudaGetSymbolAddress((void**)&w2l, q_w2_l);
    cudaGetSymbolAddress((void**)&sxn, s_xn); cudaGetSymbolAddress((void**)&sxd, s_xd);
    cudaGetSymbolAddress((void**)&sy,  s_y);  cudaGetSymbolAddress((void**)&sx2, s_x2);
    cudaGetSymbolAddress((void**)&shh, s_h);
    cudaGetSymbolAddress((void**)&swi, s_wi); cudaGetSymbolAddress((void**)&swd, s_wd);
    cudaGetSymbolAddress((void**)&swo, s_wo); cudaGetSymbolAddress((void**)&sw1, s_w1);
    cudaGetSymbolAddress((void**)&sw2, s_w2);

    const int SMEM = 2 * STG_B;   // 48 KB
    cudaFuncSetAttribute(igemm<0, 0>, cudaFuncAttributeMaxDynamicSharedMemorySize, SMEM);
    cudaFuncSetAttribute(igemm<2, 0>, cudaFuncAttributeMaxDynamicSharedMemorySize, SMEM);
    cudaFuncSetAttribute(igemm<3, 0>, cudaFuncAttributeMaxDynamicSharedMemorySize, SMEM);
    cudaFuncSetAttribute(igemm<1, 1>, cudaFuncAttributeMaxDynamicSharedMemorySize, SMEM);
    cudaFuncSetAttribute(igemm<0, 2>, cudaFuncAttributeMaxDynamicSharedMemorySize, SMEM);

    // 0. quantize weights (row-scaled int8 hi/lo)
    quant_rows<<<2 * DINNER, 128>>>(in_proj_w, DMODEL, DMODEL, wih, wil, swi);
    quant_rows<<<DINNER, 128>>>(dt_proj_w, DTRANK, DTRANK, wdh, wdl, swd);
    quant_rows<<<DMODEL, 128>>>(out_proj_w, DINNER, DINNER, woh, wol, swo);
    quant_rows<<<NEXP * HIDDEN, 128>>>(w1, DMODEL, DMODEL, w1h, w1l, sw1);
    quant_rows<<<NEXP * DMODEL, 128>>>(w2, HIDDEN, HIDDEN, w2h, w2l, sw2);

    // 1. xn = rmsnorm(x) (+ quant)
    rmsnorm_q<<<LSEQ, 256>>>(x, p_xn, xnh, xnl, sxn);
    // 2. xr = xn @ in_proj^T  (2048x4096, K=1024)  [IMMA]
    igemm<0, 0><<<dim3(16, 64), 256, SMEM>>>(xnh, xnl, sxn, DMODEL, wih, wil, swi, DMODEL,
                                             p_xr, 2 * DINNER, LSEQ, 2 * DINNER,
                                             nullptr, nullptr, 0, nullptr, nullptr);
    // 3. conv + silu
    conv_silu<<<(LSEQ * DINNER) / 256, 256>>>(p_xr, conv_w, conv_b, p_u);
    // 4. x_dbl = u @ x_proj^T (2048x96, K=2048) split-K=8 exact fp32
    gemm_sk<<<dim3(32, 2, SPLITK), 256>>>(p_u, DINNER, x_proj_w, DINNER,
                                          p_xp, XDBL, LSEQ, XDBL, DINNER / SPLITK);
    reduce_sk<<<(LSEQ * XDBL + 255) / 256, 256>>>(p_xp, p_xdbl, LSEQ * XDBL);
    quant_rows<<<LSEQ, 128>>>(p_xdbl, XDBL, DTRANK, xdh, xdl, sxd);
    // 5. delta = softplus(dt @ dt_proj^T + b)  (2048x2048, K=64)  [IMMA]
    igemm<3, 0><<<dim3(16, 32), 256, SMEM>>>(xdh, xdl, sxd, DTRANK, wdh, wdl, swd, DTRANK,
                                             p_delta, DINNER, LSEQ, DINNER,
                                             dt_proj_b, nullptr, 0, nullptr, nullptr);
    // 6. selective scan -> y fp32, then quant
    scan_kernel<<<DINNER / 8, 128>>>(p_delta, p_u, p_xdbl, A_log, Dvec, p_xr, p_y);
    quant_rows<<<LSEQ, 128>>>(p_y, DINNER, DINNER, yh, yl, sy);
    // 7. xm2 = y @ out_proj^T + xn  (2048x1024, K=2048)  [IMMA]
    igemm<2, 0><<<dim3(16, 16), 256, SMEM>>>(yh, yl, sy, DINNER, woh, wol, swo, DINNER,
                                             p_xm2, DMODEL, LSEQ, DMODEL,
                                             nullptr, p_xn, DMODEL, nullptr, nullptr);
    // 8. xm2n = rmsnorm(xm2) (+ quant)
    rmsnorm_q<<<LSEQ, 256>>>(p_xm2, p_xm2n, x2h, x2l, sx2);
    // 9. gating + routing
    gate_topk<<<LSEQ / 4, 128>>>(p_xm2n, gate_w, p_te, p_tv);
    route_zero<<<1, 32>>>(p_cnt, p_cur);
    route_count<<<LSEQ / 256, 256>>>(p_te, p_cnt);
    route_offsets<<<1, 1>>>(p_cnt, p_off);
    route_scatter<<<LSEQ / 256, 256>>>(p_te, p_tv, p_off, p_cur, p_ptok, p_pw, p_tp);
    // 10. expert GEMMs  [IMMA]
    igemm<1, 1><<<dim3(32, 64, NEXP), 256, SMEM>>>(x2h, x2l, sx2, DMODEL, w1h, w1l, sw1, DMODEL,
                                                   p_hf, HIDDEN, 0, HIDDEN,
                                                   nullptr, nullptr, 0, p_off, p_ptok);
    quant_rows<<<NPAIR, 128>>>(p_hf, HIDDEN, HIDDEN, hh, hl, shh);
    igemm<0, 2><<<dim3(32, 16, NEXP), 256, SMEM>>>(hh, hl, shh, HIDDEN, w2h, w2l, sw2, HIDDEN,
                                                   p_y2, DMODEL, 0, DMODEL,
                                                   nullptr, nullptr, 0, p_off, nullptr);
    moe_combine<<<(LSEQ * DMODEL) / 256, 256>>>(x, p_y2, p_tp, p_pw, out);
}

// round 7
// speedup vs baseline: 2.3636x; 2.3636x over previous
#include <cuda_runtime.h>
#include <cuda_fp16.h>
#include <math.h>
#include <stdint.h>

// ---------------- problem constants ----------------
#define LSEQ   2048
#define DMODEL 1024
#define DINNER 2048
#define DSTATE 16
#define DTRANK 64
#define XDBL   96
#define NEXP   8
#define HIDDEN 4096
#define NPAIR  4096
#define SPLITK 8

// ---------------- fp32 scratch ----------------
__device__ float g_xn   [LSEQ * DMODEL];
__device__ float g_xr   [LSEQ * 2 * DINNER];
__device__ float g_u    [LSEQ * DINNER];
__device__ float g_xdbl [LSEQ * XDBL];
__device__ float g_xp   [SPLITK * LSEQ * XDBL];
__device__ float g_delta[LSEQ * DINNER];
__device__ float g_xm2  [LSEQ * DMODEL];
__device__ float g_xm2n [LSEQ * DMODEL];
__device__ float g_y2   [(size_t)NPAIR * DMODEL];
__device__ int   g_top_e[LSEQ * 2];
__device__ float g_top_v[LSEQ * 2];
__device__ int   g_cnt[NEXP];
__device__ int   g_cur[NEXP];
__device__ int   g_off[NEXP + 1];
__device__ int   g_ptok[NPAIR];
__device__ float g_pw  [NPAIR];
__device__ int   g_tok_pair[LSEQ * 2];

// ---------------- fp16 scratch (activations single, weights hi/lo) ----------------
__device__ __align__(16) __half h_xn [LSEQ * DMODEL];
__device__ __align__(16) __half h_xd [LSEQ * XDBL];
__device__ __align__(16) __half h_y  [LSEQ * DINNER];
__device__ __align__(16) __half h_x2 [LSEQ * DMODEL];
__device__ __align__(16) __half h_h  [(size_t)NPAIR * HIDDEN];
__device__ __align__(16) __half h_wi_h[2 * DINNER * DMODEL], h_wi_l[2 * DINNER * DMODEL];
__device__ __align__(16) __half h_wd_h[DINNER * DTRANK],     h_wd_l[DINNER * DTRANK];
__device__ __align__(16) __half h_wo_h[DMODEL * DINNER],     h_wo_l[DMODEL * DINNER];
__device__ __align__(16) __half h_w1_h[(size_t)NEXP * HIDDEN * DMODEL], h_w1_l[(size_t)NEXP * HIDDEN * DMODEL];
__device__ __align__(16) __half h_w2_h[(size_t)NEXP * DMODEL * HIDDEN], h_w2_l[(size_t)NEXP * DMODEL * HIDDEN];

// ---------------- helpers ----------------
__device__ __forceinline__ void cpa16(uint32_t dst, const void* src)
{
    asm volatile("cp.async.cg.shared.global [%0], [%1], 16;" :: "r"(dst), "l"(src));
}

__device__ __forceinline__ void ldsm4(uint32_t* r, uint32_t a)
{
    asm volatile("ldmatrix.sync.aligned.m8n8.x4.shared.b16 {%0,%1,%2,%3}, [%4];"
                 : "=r"(r[0]), "=r"(r[1]), "=r"(r[2]), "=r"(r[3]) : "r"(a));
}

__device__ __forceinline__ void hmma(float* d, const uint32_t* a, const uint32_t* b)
{
    asm volatile(
        "mma.sync.aligned.m16n8k16.row.col.f32.f16.f16.f32 "
        "{%0,%1,%2,%3},{%4,%5,%6,%7},{%8,%9},{%0,%1,%2,%3};\n"
        : "+f"(d[0]), "+f"(d[1]), "+f"(d[2]), "+f"(d[3])
        : "r"(a[0]), "r"(a[1]), "r"(a[2]), "r"(a[3]), "r"(b[0]), "r"(b[1]));
}

// ---------------- weight splitter: w -> fp16 hi + fp16 residual ----------------
__global__ void split_h(const float4* __restrict__ src, uint2* __restrict__ hi,
                        uint2* __restrict__ lo, int n4)
{
    int i = blockIdx.x * 256 + threadIdx.x;
    if (i >= n4) return;
    float4 v = src[i];
    __half hx = __float2half_rn(v.x), hy = __float2half_rn(v.y);
    __half hz = __float2half_rn(v.z), hw = __float2half_rn(v.w);
    __half lx = __float2half_rn(v.x - __half2float(hx));
    __half ly = __float2half_rn(v.y - __half2float(hy));
    __half lz = __float2half_rn(v.z - __half2float(hz));
    __half lw = __float2half_rn(v.w - __half2float(hw));
    __half2 h01 = __halves2half2(hx, hy), h23 = __halves2half2(hz, hw);
    __half2 l01 = __halves2half2(lx, ly), l23 = __halves2half2(lz, lw);
    hi[i] = make_uint2(*(uint32_t*)&h01, *(uint32_t*)&h23);
    lo[i] = make_uint2(*(uint32_t*)&l01, *(uint32_t*)&l23);
}

// ---------------- fp16 2-term tensor GEMM: C = epi(A @ (Wh+Wl)^T) ----------------
// A: (M,K) fp16 row-major stride lda. W: (N,K) fp16 hi/lo stride K.
// CTA tile 128x128, k-stage 32, cp.async double buffer, ldmatrix frags.
// 8 warps: 2m x 4n, warp tile 64x32.
// EPI: 0 store fp32, 1 gelu->fp16, 2 +addsrc fp32, 3 softplus(+bias) fp32
// MODE: 0 plain, 1 gather A rows via ptok + per-expert W, 2 contiguous expert rows
#define STG_B 24576
template<int EPI, int MODE>
__global__ void __launch_bounds__(256, 2) hgemm(
    const __half* __restrict__ Aq, int lda,
    const __half* __restrict__ Whi, const __half* __restrict__ Wlo, int K,
    float* __restrict__ C, int ldc, int M, int N,
    const float* __restrict__ bias, const float* __restrict__ addsrc, int ldadd,
    const int* __restrict__ off, const int* __restrict__ ptok,
    __half* __restrict__ Ch)
{
    extern __shared__ __align__(16) uint8_t smem[];
    int base = 0, rows = M;
    const __half *Wh = Whi, *Wl = Wlo;
    if (MODE != 0) {
        int e = blockIdx.z;
        base = off[e];
        rows = off[e + 1] - base;
        Wh += (size_t)e * (size_t)N * K;
        Wl += (size_t)e * (size_t)N * K;
    }
    int m0 = blockIdx.x * 128;
    if (m0 >= rows) return;
    int n0 = blockIdx.y * 128;

    int tid = threadIdx.x;
    int wid = tid >> 5, lane = tid & 31;
    int lr = lane >> 2, lc = lane & 3;
    int warp_m = wid >> 2, warp_n = wid & 3;

    // ---- global load mapping: 2 rows per thread per tile, 16B segment qg ----
    int qg = tid & 3;
    int ar = tid >> 2;                 // 0..63
    int rA0 = m0 + ar, rA1 = rA0 + 64;
    int c0 = rA0 < rows ? rA0 : rows - 1;
    int c1 = rA1 < rows ? rA1 : rows - 1;
    int gA0, gA1;
    if (MODE == 1)      { gA0 = ptok[base + c0]; gA1 = ptok[base + c1]; }
    else if (MODE == 2) { gA0 = base + c0;       gA1 = base + c1; }
    else                { gA0 = c0;              gA1 = c1; }

    const __half* pA0 = Aq + (size_t)gA0 * lda + qg * 8;
    const __half* pA1 = Aq + (size_t)gA1 * lda + qg * 8;
    const __half* pBh0 = Wh + (size_t)(n0 + ar) * K + qg * 8;
    const __half* pBh1 = Wh + (size_t)(n0 + ar + 64) * K + qg * 8;
    const __half* pBl0 = Wl + (size_t)(n0 + ar) * K + qg * 8;
    const __half* pBl1 = Wl + (size_t)(n0 + ar + 64) * K + qg * 8;

    uint32_t sb0 = (uint32_t)__cvta_generic_to_shared(smem);
    int dst0 = ar * 64 + ((qg ^ ((ar >> 1) & 3)) << 4);
    int dst1 = dst0 + 4096;   // row+64: same swizzle phase

    // ---- per-lane ldmatrix addresses (byte offsets within stage) ----
    int rA = warp_m * 64 + (lane & 15);
    int swzA = (rA >> 1) & 3;
    int aoff0 = rA * 64 + ((((lane >> 4)) ^ swzA) << 4);        // sub0 segs 0/1
    int aoff1 = rA * 64 + (((2 + (lane >> 4)) ^ swzA) << 4);    // sub1 segs 2/3
    int rB = warp_n * 32 + (lane & 7) + ((lane >> 4) << 3);
    int swzB = (rB >> 1) & 3;
    int boff0 = rB * 64 + ((((lane >> 3) & 1) ^ swzB) << 4);
    int boff1 = rB * 64 + (((2 + ((lane >> 3) & 1)) ^ swzB) << 4);

    float acc[4][4][4];
    #pragma unroll
    for (int i = 0; i < 4; i++)
        #pragma unroll
        for (int j = 0; j < 4; j++)
            #pragma unroll
            for (int r = 0; r < 4; r++) acc[i][j][r] = 0.f;

    int nt = K >> 5;
    // prologue
    {
        cpa16(sb0 + 0     + dst0, pA0);
        cpa16(sb0 + 0     + dst1, pA1);
        cpa16(sb0 + 8192  + dst0, pBh0);
        cpa16(sb0 + 8192  + dst1, pBh1);
        cpa16(sb0 + 16384 + dst0, pBl0);
        cpa16(sb0 + 16384 + dst1, pBl1);
        asm volatile("cp.async.commit_group;");
    }
    for (int t = 0; t < nt; t++) {
        __syncthreads();
        if (t + 1 < nt) {
            int kc = (t + 1) << 5;
            uint32_t s = sb0 + ((t + 1) & 1) * STG_B;
            cpa16(s + 0     + dst0, pA0 + kc);
            cpa16(s + 0     + dst1, pA1 + kc);
            cpa16(s + 8192  + dst0, pBh0 + kc);
            cpa16(s + 8192  + dst1, pBh1 + kc);
            cpa16(s + 16384 + dst0, pBl0 + kc);
            cpa16(s + 16384 + dst1, pBl1 + kc);
        }
        asm volatile("cp.async.commit_group;");
        asm volatile("cp.async.wait_group 1;");
        __syncthreads();

        uint32_t S = sb0 + (t & 1) * STG_B;
        #pragma unroll
        for (int sub = 0; sub < 2; sub++) {
            uint32_t aadr = S + (sub ? aoff1 : aoff0);
            uint32_t badr = (sub ? boff1 : boff0);
            uint32_t ah[4][4];
            #pragma unroll
            for (int im = 0; im < 4; im++) ldsm4(ah[im], aadr + im * 1024);
            uint32_t bh0[4], bh1[4], bl0[4], bl1[4];
            ldsm4(bh0, S + 8192  + badr);
            ldsm4(bh1, S + 8192  + badr + 1024);
            ldsm4(bl0, S + 16384 + badr);
            ldsm4(bl1, S + 16384 + badr + 1024);
            #pragma unroll
            for (int im = 0; im < 4; im++) {
                hmma(acc[im][0], ah[im], bh0);
                hmma(acc[im][0], ah[im], bl0);
                hmma(acc[im][1], ah[im], bh0 + 2);
                hmma(acc[im][1], ah[im], bl0 + 2);
                hmma(acc[im][2], ah[im], bh1);
                hmma(acc[im][2], ah[im], bl1);
                hmma(acc[im][3], ah[im], bh1 + 2);
                hmma(acc[im][3], ah[im], bl1 + 2);
            }
        }
    }

    // ---- epilogue ----
    #pragma unroll
    for (int im = 0; im < 4; im++) {
        #pragma unroll
        for (int half = 0; half < 2; half++) {
            int m = m0 + warp_m * 64 + im * 16 + lr + half * 8;
            if (m >= rows) continue;
            size_t crow = (size_t)(base + m) * (MODE == 0 ? (size_t)ldc : (size_t)ldc);
            if (MODE == 0) crow = (size_t)m * ldc;
            #pragma unroll
            for (int in = 0; in < 4; in++) {
                int n = n0 + warp_n * 32 + in * 8 + lc * 2;
                float v0 = acc[im][in][half * 2];
                float v1 = acc[im][in][half * 2 + 1];
                if (EPI == 1) {
                    v0 = 0.5f * v0 * (1.0f + erff(v0 * 0.70710678118654752f));
                    v1 = 0.5f * v1 * (1.0f + erff(v1 * 0.70710678118654752f));
                    __half2 hv = __halves2half2(__float2half_rn(v0), __float2half_rn(v1));
                    *(__half2*)(Ch + crow + n) = hv;
                } else {
                    if (EPI == 2) {
                        v0 += addsrc[(size_t)m * ldadd + n];
                        v1 += addsrc[(size_t)m * ldadd + n + 1];
                    } else if (EPI == 3) {
                        float z0 = v0 + bias[n], z1 = v1 + bias[n + 1];
                        v0 = (z0 > 20.f) ? z0 : log1pf(__expf(z0));
                        v1 = (z1 > 20.f) ? z1 : log1pf(__expf(z1));
                    }
                    *(float2*)(C + crow + n) = make_float2(v0, v1);
                }
            }
        }
    }
}

// ---------------- rmsnorm (writes fp32 + fp16) ----------------
__global__ void rmsnorm_h(const float* __restrict__ x, float* __restrict__ o,
                          __half* __restrict__ oh)
{
    int row = blockIdx.x;
    const float4* xp = (const float4*)(x + (size_t)row * DMODEL);
    float4 v = xp[threadIdx.x];
    float s = v.x * v.x + v.y * v.y + v.z * v.z + v.w * v.w;
    __shared__ float ssum[8];
    #pragma unroll
    for (int off = 16; off; off >>= 1) s += __shfl_xor_sync(0xffffffffu, s, off);
    if ((threadIdx.x & 31) == 0) ssum[threadIdx.x >> 5] = s;
    __syncthreads();
    if (threadIdx.x < 8) {
        float t = ssum[threadIdx.x];
        #pragma unroll
        for (int off = 4; off; off >>= 1) t += __shfl_xor_sync(0xffu, t, off);
        if (threadIdx.x == 0) ssum[0] = t;
    }
    __syncthreads();
    float scale = 32.0f / fmaxf(sqrtf(ssum[0]), 1e-12f);
    float4 w = make_float4(v.x * scale, v.y * scale, v.z * scale, v.w * scale);
    ((float4*)(o + (size_t)row * DMODEL))[threadIdx.x] = w;
    __half2 h01 = __halves2half2(__float2half_rn(w.x), __float2half_rn(w.y));
    __half2 h23 = __halves2half2(__float2half_rn(w.z), __float2half_rn(w.w));
    ((uint2*)(oh + (size_t)row * DMODEL))[threadIdx.x] =
        make_uint2(*(uint32_t*)&h01, *(uint32_t*)&h23);
}

// ---------------- split-K SIMT GEMM for skinny x_proj (exact fp32) ----------------
__global__ void __launch_bounds__(256) gemm_sk(
    const float* __restrict__ A, int lda,
    const float* __restrict__ W, int ldw,
    float* __restrict__ Cpart, int ldc,
    int M, int N, int kchunk)
{
    int koff = blockIdx.z * kchunk;
    float* C = Cpart + (size_t)blockIdx.z * M * ldc;
    __shared__ float As[16][68];
    __shared__ float Bs[16][68];
    int tid = threadIdx.x;
    int m0 = blockIdx.x * 64, n0 = blockIdx.y * 64;
    int tx = tid & 15, ty = tid >> 4;
    int lr = tid >> 2;
    int lk = (tid & 3) << 2;
    int am = m0 + lr;
    int wn = n0 + lr;
    bool a_ok = am < M;
    bool w_ok = wn < N;
    const float* Arow = A + (size_t)(a_ok ? am : 0) * lda + koff;
    const float* Wrow = W + (size_t)(w_ok ? wn : 0) * ldw + koff;
    float acc[4][4] = {};
    for (int k0 = 0; k0 < kchunk; k0 += 16) {
        float4 av = a_ok ? *(const float4*)(Arow + k0 + lk) : make_float4(0, 0, 0, 0);
        float4 wv = w_ok ? *(const float4*)(Wrow + k0 + lk) : make_float4(0, 0, 0, 0);
        __syncthreads();
        As[lk][lr] = av.x; As[lk + 1][lr] = av.y; As[lk + 2][lr] = av.z; As[lk + 3][lr] = av.w;
        Bs[lk][lr] = wv.x; Bs[lk + 1][lr] = wv.y; Bs[lk + 2][lr] = wv.z; Bs[lk + 3][lr] = wv.w;
        __syncthreads();
        #pragma unroll
        for (int k = 0; k < 16; k++) {
            float a[4], b[4];
            #pragma unroll
            for (int i = 0; i < 4; i++) a[i] = As[k][ty * 4 + i];
            #pragma unroll
            for (int j = 0; j < 4; j++) b[j] = Bs[k][tx * 4 + j];
            #pragma unroll
            for (int i = 0; i < 4; i++)
                #pragma unroll
                for (int j = 0; j < 4; j++)
                    acc[i][j] += a[i] * b[j];
        }
    }
    #pragma unroll
    for (int i = 0; i < 4; i++) {
        int m = m0 + ty * 4 + i;
        if (m >= M) continue;
        #pragma unroll
        for (int j = 0; j < 4; j++) {
            int n = n0 + tx * 4 + j;
            if (n >= N) continue;
            C[(size_t)m * ldc + n] = acc[i][j];
        }
    }
}

__global__ void reduce_sk(const float* __restrict__ p, float* __restrict__ o,
                          __half* __restrict__ oh, int n)
{
    int i = blockIdx.x * 256 + threadIdx.x;
    if (i >= n) return;
    float s = 0.f;
    #pragma unroll
    for (int j = 0; j < SPLITK; j++) s += p[i + (size_t)j * n];
    o[i] = s;
    oh[i] = __float2half_rn(s);
}

// ---------------- causal depthwise conv(4) + silu ----------------
__global__ void conv_silu(const float* __restrict__ xr, const float* __restrict__ cw,
                          const float* __restrict__ cb, float* __restrict__ u)
{
    int idx = blockIdx.x * 256 + threadIdx.x;
    int t = idx >> 11, d = idx & (DINNER - 1);
    float w0 = cw[d * 4], w1 = cw[d * 4 + 1], w2 = cw[d * 4 + 2], w3 = cw[d * 4 + 3];
    float s = cb[d];
    const float* col = xr + d;
    if (t >= 3) s += col[(size_t)(t - 3) * (2 * DINNER)] * w0;
    if (t >= 2) s += col[(size_t)(t - 2) * (2 * DINNER)] * w1;
    if (t >= 1) s += col[(size_t)(t - 1) * (2 * DINNER)] * w2;
    s += col[(size_t)t * (2 * DINNER)] * w3;
    u[idx] = s / (1.f + __expf(-s));
}

// ---------------- selective scan (fp16 y out) ----------------
__global__ void scan_kernel(const float* __restrict__ delta,
                            const float* __restrict__ u,
                            const float* __restrict__ xdbl,
                            const float* __restrict__ A_log,
                            const float* __restrict__ Dvec,
                            const float* __restrict__ xr,
                            __half* __restrict__ yh)
{
    int lane16 = threadIdx.x & 15;
    int ch = threadIdx.x >> 4;
    int d = blockIdx.x * 8 + ch;
    float A = -__expf(A_log[d * DSTATE + lane16]);
    float Dd = Dvec[d];
    float h = 0.f;
    __shared__ float sB[32][16], sC[32][16], sdl[32][8], su[32][8], sre[32][8];
    for (int t0 = 0; t0 < LSEQ; t0 += 32) {
        __syncthreads();
        for (int i = threadIdx.x; i < 512; i += 128) {
            int tt = i >> 4, n = i & 15;
            const float* xb = xdbl + (size_t)(t0 + tt) * XDBL;
            sB[tt][n] = xb[DTRANK + n];
            sC[tt][n] = xb[DTRANK + DSTATE + n];
        }
        for (int i = threadIdx.x; i < 256; i += 128) {
            int tt = i >> 3, c = i & 7;
            int dd = blockIdx.x * 8 + c;
            size_t off = (size_t)(t0 + tt) * DINNER + dd;
            sdl[tt][c] = delta[off];
            su[tt][c]  = u[off];
            sre[tt][c] = xr[(size_t)(t0 + tt) * (2 * DINNER) + DINNER + dd];
        }
        __syncthreads();
        for (int tt = 0; tt < 32; tt++) {
            float dl = sdl[tt][ch];
            float uu = su[tt][ch];
            float dA = __expf(dl * A);
            h = dA * h + dl * sB[tt][lane16] * uu;
            float p = h * sC[tt][lane16];
            #pragma unroll
            for (int o = 8; o; o >>= 1) p += __shfl_xor_sync(0xffffffffu, p, o, 16);
            if (lane16 == 0) {
                float yv = p + uu * Dd;
                float r = sre[tt][ch];
                yv *= r / (1.f + __expf(-r));
                yh[(size_t)(t0 + tt) * DINNER + d] = __float2half_rn(yv);
            }
        }
    }
}

// ---------------- gating: GEMV + softmax + top-2 ----------------
__global__ void gate_topk(const float* __restrict__ X, const float* __restrict__ gw,
                          int* __restrict__ te, float* __restrict__ tv)
{
    __shared__ float sg[NEXP * DMODEL];
    for (int i = threadIdx.x; i < NEXP * DMODEL; i += 128) sg[i] = gw[i];
    __syncthreads();
    int warp = threadIdx.x >> 5, lane = threadIdx.x & 31;
    int t = blockIdx.x * 4 + warp;
    const float* xp = X + (size_t)t * DMODEL;
    float acc[NEXP] = {};
    for (int k = lane; k < DMODEL; k += 32) {
        float xv = xp[k];
        #pragma unroll
        for (int e = 0; e < NEXP; e++) acc[e] += xv * sg[e * DMODEL + k];
    }
    #pragma unroll
    for (int e = 0; e < NEXP; e++)
        #pragma unroll
        for (int o = 16; o; o >>= 1) acc[e] += __shfl_xor_sync(0xffffffffu, acc[e], o);
    if (lane == 0) {
        float m = acc[0];
        #pragma unroll
        for (int e = 1; e < NEXP; e++) m = fmaxf(m, acc[e]);
        float g[NEXP];
        #pragma unroll
        for (int e = 0; e < NEXP; e++) g[e] = __expf(acc[e] - m);
        int i0 = 0;
        #pragma unroll
        for (int e = 1; e < NEXP; e++) if (g[e] > g[i0]) i0 = e;
        int i1 = (i0 == 0) ? 1 : 0;
        #pragma unroll
        for (int e = 0; e < NEXP; e++) if (e != i0 && g[e] > g[i1]) i1 = e;
        float inv = 1.f / (g[i0] + g[i1]);
        te[t * 2] = i0; te[t * 2 + 1] = i1;
        tv[t * 2] = g[i0] * inv; tv[t * 2 + 1] = g[i1] * inv;
    }
}

// ---------------- routing ----------------
__global__ void route_zero(int* cnt, int* cur)
{
    if (threadIdx.x < NEXP) { cnt[threadIdx.x] = 0; cur[threadIdx.x] = 0; }
}
__global__ void route_count(const int* __restrict__ te, int* cnt)
{
    int t = blockIdx.x * 256 + threadIdx.x;
    atomicAdd(&cnt[te[t * 2]], 1);
    atomicAdd(&cnt[te[t * 2 + 1]], 1);
}
__global__ void route_offsets(const int* __restrict__ cnt, int* off)
{
    int s = 0;
    for (int e = 0; e < NEXP; e++) { off[e] = s; s += cnt[e]; }
    off[NEXP] = s;
}
__global__ void route_scatter(const int* __restrict__ te, const float* __restrict__ tv,
                              const int* __restrict__ off, int* cur,
                              int* ptok, float* pw, int* tok_pair)
{
    int t = blockIdx.x * 256 + threadIdx.x;
    #pragma unroll
    for (int k = 0; k < 2; k++) {
        int e = te[t * 2 + k];
        int pos = atomicAdd(&cur[e], 1);
        int p = off[e] + pos;
        ptok[p] = t;
        pw[p] = tv[t * 2 + k];
        tok_pair[t * 2 + k] = p;
    }
}

// ---------------- final combine ----------------
__global__ void moe_combine(const float* __restrict__ x, const float* __restrict__ y2,
                            const int* __restrict__ tok_pair, const float* __restrict__ pw,
                            float* __restrict__ out)
{
    int i = blockIdx.x * 256 + threadIdx.x;
    int t = i >> 10, n = i & (DMODEL - 1);
    int p0 = tok_pair[t * 2], p1 = tok_pair[t * 2 + 1];
    out[i] = x[i] + pw[p0] * y2[(size_t)p0 * DMODEL + n]
                  + pw[p1] * y2[(size_t)p1 * DMODEL + n];
}

// ---------------- launch ----------------
extern "C" void kernel_launch(void* const* d_in, const int* in_sizes, int n_in,
                              void* d_out, int out_size)
{
    (void)in_sizes; (void)n_in; (void)out_size;
    const float* x          = (const float*)d_in[0];
    const float* in_proj_w  = (const float*)d_in[1];
    const float* conv_w     = (const float*)d_in[2];
    const float* conv_b     = (const float*)d_in[3];
    const float* x_proj_w   = (const float*)d_in[4];
    const float* dt_proj_w  = (const float*)d_in[5];
    const float* dt_proj_b  = (const float*)d_in[6];
    const float* A_log      = (const float*)d_in[7];
    const float* Dvec       = (const float*)d_in[8];
    const float* out_proj_w = (const float*)d_in[9];
    const float* gate_w     = (const float*)d_in[10];
    const float* w1         = (const float*)d_in[11];
    const float* w2         = (const float*)d_in[12];
    float* out = (float*)d_out;

    float *p_xn, *p_xr, *p_u, *p_xdbl, *p_xp, *p_delta, *p_xm2, *p_xm2n, *p_y2, *p_tv, *p_pw;
    int *p_te, *p_cnt, *p_cur, *p_off, *p_ptok, *p_tp;
    cudaGetSymbolAddress((void**)&p_xn, g_xn);
    cudaGetSymbolAddress((void**)&p_xr, g_xr);
    cudaGetSymbolAddress((void**)&p_u, g_u);
    cudaGetSymbolAddress((void**)&p_xdbl, g_xdbl);
    cudaGetSymbolAddress((void**)&p_xp, g_xp);
    cudaGetSymbolAddress((void**)&p_delta, g_delta);
    cudaGetSymbolAddress((void**)&p_xm2, g_xm2);
    cudaGetSymbolAddress((void**)&p_xm2n, g_xm2n);
    cudaGetSymbolAddress((void**)&p_y2, g_y2);
    cudaGetSymbolAddress((void**)&p_te, g_top_e);
    cudaGetSymbolAddress((void**)&p_tv, g_top_v);
    cudaGetSymbolAddress((void**)&p_cnt, g_cnt);
    cudaGetSymbolAddress((void**)&p_cur, g_cur);
    cudaGetSymbolAddress((void**)&p_off, g_off);
    cudaGetSymbolAddress((void**)&p_ptok, g_ptok);
    cudaGetSymbolAddress((void**)&p_pw, g_pw);
    cudaGetSymbolAddress((void**)&p_tp, g_tok_pair);

    __half *xnh, *xdh, *yh, *x2h, *hh;
    __half *wih, *wil, *wdh, *wdl, *woh, *wol, *w1h, *w1l, *w2h, *w2l;
    cudaGetSymbolAddress((void**)&xnh, h_xn);
    cudaGetSymbolAddress((void**)&xdh, h_xd);
    cudaGetSymbolAddress((void**)&yh,  h_y);
    cudaGetSymbolAddress((void**)&x2h, h_x2);
    cudaGetSymbolAddress((void**)&hh,  h_h);
    cudaGetSymbolAddress((void**)&wih, h_wi_h); cudaGetSymbolAddress((void**)&wil, h_wi_l);
    cudaGetSymbolAddress((void**)&wdh, h_wd_h); cudaGetSymbolAddress((void**)&wdl, h_wd_l);
    cudaGetSymbolAddress((void**)&woh, h_wo_h); cudaGetSymbolAddress((void**)&wol, h_wo_l);
    cudaGetSymbolAddress((void**)&w1h, h_w1_h); cudaGetSymbolAddress((void**)&w1l, h_w1_l);
    cudaGetSymbolAddress((void**)&w2h, h_w2_h); cudaGetSymbolAddress((void**)&w2l, h_w2_l);

    const int SMEM = 2 * STG_B;   // 48 KB
    cudaFuncSetAttribute(hgemm<0, 0>, cudaFuncAttributeMaxDynamicSharedMemorySize, SMEM);
    cudaFuncSetAttribute(hgemm<2, 0>, cudaFuncAttributeMaxDynamicSharedMemorySize, SMEM);
    cudaFuncSetAttribute(hgemm<3, 0>, cudaFuncAttributeMaxDynamicSharedMemorySize, SMEM);
    cudaFuncSetAttribute(hgemm<1, 1>, cudaFuncAttributeMaxDynamicSharedMemorySize, SMEM);
    cudaFuncSetAttribute(hgemm<0, 2>, cudaFuncAttributeMaxDynamicSharedMemorySize, SMEM);

    // 0. split weights to fp16 hi/lo
    split_h<<<(2 * DINNER * DMODEL / 4 + 255) / 256, 256>>>((const float4*)in_proj_w, (uint2*)wih, (uint2*)wil, 2 * DINNER * DMODEL / 4);
    split_h<<<(DINNER * DTRANK / 4 + 255) / 256, 256>>>((const float4*)dt_proj_w, (uint2*)wdh, (uint2*)wdl, DINNER * DTRANK / 4);
    split_h<<<(DMODEL * DINNER / 4 + 255) / 256, 256>>>((const float4*)out_proj_w, (uint2*)woh, (uint2*)wol, DMODEL * DINNER / 4);
    split_h<<<(int)((size_t)NEXP * HIDDEN * DMODEL / 4 + 255) / 256, 256>>>((const float4*)w1, (uint2*)w1h, (uint2*)w1l, NEXP * HIDDEN * DMODEL / 4);
    split_h<<<(int)((size_t)NEXP * DMODEL * HIDDEN / 4 + 255) / 256, 256>>>((const float4*)w2, (uint2*)w2h, (uint2*)w2l, NEXP * DMODEL * HIDDEN / 4);

    // 1. xn = rmsnorm(x)
    rmsnorm_h<<<LSEQ, 256>>>(x, p_xn, xnh);
    // 2. xr = xn @ in_proj^T (2048x4096, K=1024)
    hgemm<0, 0><<<dim3(16, 32), 256, SMEM>>>(xnh, DMODEL, wih, wil, DMODEL,
                                             p_xr, 2 * DINNER, LSEQ, 2 * DINNER,
                                             nullptr, nullptr, 0, nullptr, nullptr, nullptr);
    // 3. conv + silu
    conv_silu<<<(LSEQ * DINNER) / 256, 256>>>(p_xr, conv_w, conv_b, p_u);
    // 4. x_dbl = u @ x_proj^T (2048x96, K=2048) split-K exact fp32
    gemm_sk<<<dim3(32, 2, SPLITK), 256>>>(p_u, DINNER, x_proj_w, DINNER,
                                          p_xp, XDBL, LSEQ, XDBL, DINNER / SPLITK);
    reduce_sk<<<(LSEQ * XDBL + 255) / 256, 256>>>(p_xp, p_xdbl, xdh, LSEQ * XDBL);
    // 5. delta = softplus(dt @ dt_proj^T + b) (2048x2048, K=64)
    hgemm<3, 0><<<dim3(16, 16), 256, SMEM>>>(xdh, XDBL, wdh, wdl, DTRANK,
                                             p_delta, DINNER, LSEQ, DINNER,
                                             dt_proj_b, nullptr, 0, nullptr, nullptr, nullptr);
    // 6. selective scan -> y fp16
    scan_kernel<<<DINNER / 8, 128>>>(p_delta, p_u, p_xdbl, A_log, Dvec, p_xr, yh);
    // 7. xm2 = y @ out_proj^T + xn (2048x1024, K=2048)
    hgemm<2, 0><<<dim3(16, 8), 256, SMEM>>>(yh, DINNER, woh, wol, DINNER,
                                            p_xm2, DMODEL, LSEQ, DMODEL,
                                            nullptr, p_xn, DMODEL, nullptr, nullptr, nullptr);
    // 8. xm2n = rmsnorm(xm2)
    rmsnorm_h<<<LSEQ, 256>>>(p_xm2, p_xm2n, x2h);
    // 9. gating + routing
    gate_topk<<<LSEQ / 4, 128>>>(p_xm2n, gate_w, p_te, p_tv);
    route_zero<<<1, 32>>>(p_cnt, p_cur);
    route_count<<<LSEQ / 256, 256>>>(p_te, p_cnt);
    route_offsets<<<1, 1>>>(p_cnt, p_off);
    route_scatter<<<LSEQ / 256, 256>>>(p_te, p_tv, p_off, p_cur, p_ptok, p_pw, p_tp);
    // 10. expert GEMMs
    hgemm<1, 1><<<dim3(32, 32, NEXP), 256, SMEM>>>(x2h, DMODEL, w1h, w1l, DMODEL,
                                                   nullptr, HIDDEN, 0, HIDDEN,
                                                   nullptr, nullptr, 0, p_off, p_ptok, hh);
    hgemm<0, 2><<<dim3(32, 8, NEXP), 256, SMEM>>>(hh, HIDDEN, w2h, w2l, HIDDEN,
                                                  p_y2, DMODEL, 0, DMODEL,
                                                  nullptr, nullptr, 0, p_off, nullptr, nullptr);
    moe_combine<<<(LSEQ * DMODEL) / 256, 256>>>(x, p_y2, p_tp, p_pw, out);
}

// round 8
// speedup vs baseline: 2.8796x; 1.2183x over previous
#include <cuda_runtime.h>
#include <cuda_fp16.h>
#include <math.h>
#include <stdint.h>

// ---------------- problem constants ----------------
#define LSEQ   2048
#define DMODEL 1024
#define DINNER 2048
#define DSTATE 16
#define DTRANK 64
#define XDBL   96
#define NEXP   8
#define HIDDEN 4096
#define NPAIR  4096
#define SPLITK 8

// ---------------- fp32 scratch ----------------
__device__ float g_xn   [LSEQ * DMODEL];
__device__ float g_xr   [LSEQ * 2 * DINNER];
__device__ float g_u    [LSEQ * DINNER];
__device__ float g_xdbl [LSEQ * XDBL];
__device__ float g_xp   [SPLITK * LSEQ * XDBL];
__device__ float g_delta[LSEQ * DINNER];
__device__ float g_xm2  [LSEQ * DMODEL];
__device__ float g_xm2n [LSEQ * DMODEL];
__device__ float g_y2   [(size_t)NPAIR * DMODEL];
__device__ int   g_top_e[LSEQ * 2];
__device__ float g_top_v[LSEQ * 2];
__device__ int   g_cnt[NEXP];
__device__ int   g_cur[NEXP];
__device__ int   g_off[NEXP + 1];
__device__ int   g_ptok[NPAIR];
__device__ float g_pw  [NPAIR];
__device__ int   g_tok_pair[LSEQ * 2];

// ---------------- fp16 scratch ----------------
__device__ __align__(16) __half h_xn [LSEQ * DMODEL];
__device__ __align__(16) __half h_xd [LSEQ * XDBL];
__device__ __align__(16) __half h_y  [LSEQ * DINNER];
__device__ __align__(16) __half h_x2 [LSEQ * DMODEL];
__device__ __align__(16) __half h_h  [(size_t)NPAIR * HIDDEN];
__device__ __align__(16) __half h_wi [2 * DINNER * DMODEL];
__device__ __align__(16) __half h_wd [DINNER * DTRANK];
__device__ __align__(16) __half h_wo [DMODEL * DINNER];
__device__ __align__(16) __half h_w1 [(size_t)NEXP * HIDDEN * DMODEL];
__device__ __align__(16) __half h_w2 [(size_t)NEXP * DMODEL * HIDDEN];

// ---------------- helpers ----------------
__device__ __forceinline__ void cpa16(uint32_t dst, const void* src)
{
    asm volatile("cp.async.cg.shared.global [%0], [%1], 16;" :: "r"(dst), "l"(src));
}

__device__ __forceinline__ void ldsm4(uint32_t* r, uint32_t a)
{
    asm volatile("ldmatrix.sync.aligned.m8n8.x4.shared.b16 {%0,%1,%2,%3}, [%4];"
                 : "=r"(r[0]), "=r"(r[1]), "=r"(r[2]), "=r"(r[3]) : "r"(a));
}

__device__ __forceinline__ void hmma(float* d, const uint32_t* a, const uint32_t* b)
{
    asm volatile(
        "mma.sync.aligned.m16n8k16.row.col.f32.f16.f16.f32 "
        "{%0,%1,%2,%3},{%4,%5,%6,%7},{%8,%9},{%0,%1,%2,%3};\n"
        : "+f"(d[0]), "+f"(d[1]), "+f"(d[2]), "+f"(d[3])
        : "r"(a[0]), "r"(a[1]), "r"(a[2]), "r"(a[3]), "r"(b[0]), "r"(b[1]));
}

// ---------------- weight convert: fp32 -> fp16 ----------------
__global__ void conv_h(const float4* __restrict__ src, uint2* __restrict__ dst, int n4)
{
    int i = blockIdx.x * 256 + threadIdx.x;
    if (i >= n4) return;
    float4 v = src[i];
    __half2 h01 = __halves2half2(__float2half_rn(v.x), __float2half_rn(v.y));
    __half2 h23 = __halves2half2(__float2half_rn(v.z), __float2half_rn(v.w));
    dst[i] = make_uint2(*(uint32_t*)&h01, *(uint32_t*)&h23);
}

// ---------------- fp16 tensor GEMM: C = epi(A @ W^T) ----------------
// A: (M,K) fp16 row-major stride lda. W: (N,K) fp16 stride K.
// CTA tile 128x128, k-stage 32, cp.async double buffer, ldmatrix frags.
// 8 warps: 2m x 4n, warp tile 64x32.
// EPI: 0 store fp32, 1 gelu->fp16, 2 +addsrc fp32, 3 softplus(+bias) fp32
// MODE: 0 plain, 1 gather A rows via ptok + per-expert W, 2 contiguous expert rows
#define STG_B 16384
template<int EPI, int MODE>
__global__ void __launch_bounds__(256, 2) hgemm(
    const __half* __restrict__ Aq, int lda,
    const __half* __restrict__ Wq, int K,
    float* __restrict__ C, int ldc, int M, int N,
    const float* __restrict__ bias, const float* __restrict__ addsrc, int ldadd,
    const int* __restrict__ off, const int* __restrict__ ptok,
    __half* __restrict__ Ch)
{
    extern __shared__ __align__(16) uint8_t smem[];
    int base = 0, rows = M;
    const __half* W = Wq;
    if (MODE != 0) {
        int e = blockIdx.z;
        base = off[e];
        rows = off[e + 1] - base;
        W += (size_t)e * (size_t)N * K;
    }
    int m0 = blockIdx.x * 128;
    if (m0 >= rows) return;
    int n0 = blockIdx.y * 128;

    int tid = threadIdx.x;
    int wid = tid >> 5, lane = tid & 31;
    int lr = lane >> 2, lc = lane & 3;
    int warp_m = wid >> 2, warp_n = wid & 3;

    // ---- global load mapping: 2 rows per thread per tile, 16B segment qg ----
    int qg = tid & 3;
    int ar = tid >> 2;                 // 0..63
    int rA0 = m0 + ar, rA1 = rA0 + 64;
    int c0 = rA0 < rows ? rA0 : rows - 1;
    int c1 = rA1 < rows ? rA1 : rows - 1;
    int gA0, gA1;
    if (MODE == 1)      { gA0 = ptok[base + c0]; gA1 = ptok[base + c1]; }
    else if (MODE == 2) { gA0 = base + c0;       gA1 = base + c1; }
    else                { gA0 = c0;              gA1 = c1; }

    const __half* pA0 = Aq + (size_t)gA0 * lda + qg * 8;
    const __half* pA1 = Aq + (size_t)gA1 * lda + qg * 8;
    const __half* pB0 = W + (size_t)(n0 + ar) * K + qg * 8;
    const __half* pB1 = W + (size_t)(n0 + ar + 64) * K + qg * 8;

    uint32_t sb0 = (uint32_t)__cvta_generic_to_shared(smem);
    int dst0 = ar * 64 + ((qg ^ ((ar >> 1) & 3)) << 4);
    int dst1 = dst0 + 4096;

    // ---- per-lane ldmatrix addresses (byte offsets within stage) ----
    int rA = warp_m * 64 + (lane & 15);
    int swzA = (rA >> 1) & 3;
    int aoff0 = rA * 64 + ((((lane >> 4)) ^ swzA) << 4);
    int aoff1 = rA * 64 + (((2 + (lane >> 4)) ^ swzA) << 4);
    int rB = warp_n * 32 + (lane & 7) + ((lane >> 4) << 3);
    int swzB = (rB >> 1) & 3;
    int boff0 = rB * 64 + ((((lane >> 3) & 1) ^ swzB) << 4);
    int boff1 = rB * 64 + (((2 + ((lane >> 3) & 1)) ^ swzB) << 4);

    float acc[4][4][4];
    #pragma unroll
    for (int i = 0; i < 4; i++)
        #pragma unroll
        for (int j = 0; j < 4; j++)
            #pragma unroll
            for (int r = 0; r < 4; r++) acc[i][j][r] = 0.f;

    int nt = K >> 5;
    // prologue
    {
        cpa16(sb0 + 0    + dst0, pA0);
        cpa16(sb0 + 0    + dst1, pA1);
        cpa16(sb0 + 8192 + dst0, pB0);
        cpa16(sb0 + 8192 + dst1, pB1);
        asm volatile("cp.async.commit_group;");
    }
    for (int t = 0; t < nt; t++) {
        __syncthreads();
        if (t + 1 < nt) {
            int kc = (t + 1) << 5;
            uint32_t s = sb0 + ((t + 1) & 1) * STG_B;
            cpa16(s + 0    + dst0, pA0 + kc);
            cpa16(s + 0    + dst1, pA1 + kc);
            cpa16(s + 8192 + dst0, pB0 + kc);
            cpa16(s + 8192 + dst1, pB1 + kc);
        }
        asm volatile("cp.async.commit_group;");
        asm volatile("cp.async.wait_group 1;");
        __syncthreads();

        uint32_t S = sb0 + (t & 1) * STG_B;
        #pragma unroll
        for (int sub = 0; sub < 2; sub++) {
            uint32_t aadr = S + (sub ? aoff1 : aoff0);
            uint32_t badr = S + 8192 + (sub ? boff1 : boff0);
            uint32_t ah[4][4];
            #pragma unroll
            for (int im = 0; im < 4; im++) ldsm4(ah[im], aadr + im * 1024);
            uint32_t b0[4], b1[4];
            ldsm4(b0, badr);
            ldsm4(b1, badr + 1024);
            #pragma unroll
            for (int im = 0; im < 4; im++) {
                hmma(acc[im][0], ah[im], b0);
                hmma(acc[im][1], ah[im], b0 + 2);
                hmma(acc[im][2], ah[im], b1);
                hmma(acc[im][3], ah[im], b1 + 2);
            }
        }
    }

    // ---- epilogue ----
    #pragma unroll
    for (int im = 0; im < 4; im++) {
        #pragma unroll
        for (int half = 0; half < 2; half++) {
            int m = m0 + warp_m * 64 + im * 16 + lr + half * 8;
            if (m >= rows) continue;
            size_t crow = (size_t)(base + m) * (size_t)ldc;
            if (MODE == 0) crow = (size_t)m * ldc;
            #pragma unroll
            for (int in = 0; in < 4; in++) {
                int n = n0 + warp_n * 32 + in * 8 + lc * 2;
                float v0 = acc[im][in][half * 2];
                float v1 = acc[im][in][half * 2 + 1];
                if (EPI == 1) {
                    v0 = 0.5f * v0 * (1.0f + erff(v0 * 0.70710678118654752f));
                    v1 = 0.5f * v1 * (1.0f + erff(v1 * 0.70710678118654752f));
                    __half2 hv = __halves2half2(__float2half_rn(v0), __float2half_rn(v1));
                    *(__half2*)(Ch + crow + n) = hv;
                } else {
                    if (EPI == 2) {
                        v0 += addsrc[(size_t)m * ldadd + n];
                        v1 += addsrc[(size_t)m * ldadd + n + 1];
                    } else if (EPI == 3) {
                        float z0 = v0 + bias[n], z1 = v1 + bias[n + 1];
                        v0 = (z0 > 20.f) ? z0 : log1pf(__expf(z0));
                        v1 = (z1 > 20.f) ? z1 : log1pf(__expf(z1));
                    }
                    *(float2*)(C + crow + n) = make_float2(v0, v1);
                }
            }
        }
    }
}

// ---------------- rmsnorm (writes fp32 + fp16) ----------------
__global__ void rmsnorm_h(const float* __restrict__ x, float* __restrict__ o,
                          __half* __restrict__ oh)
{
    int row = blockIdx.x;
    const float4* xp = (const float4*)(x + (size_t)row * DMODEL);
    float4 v = xp[threadIdx.x];
    float s = v.x * v.x + v.y * v.y + v.z * v.z + v.w * v.w;
    __shared__ float ssum[8];
    #pragma unroll
    for (int off = 16; off; off >>= 1) s += __shfl_xor_sync(0xffffffffu, s, off);
    if ((threadIdx.x & 31) == 0) ssum[threadIdx.x >> 5] = s;
    __syncthreads();
    if (threadIdx.x < 8) {
        float t = ssum[threadIdx.x];
        #pragma unroll
        for (int off = 4; off; off >>= 1) t += __shfl_xor_sync(0xffu, t, off);
        if (threadIdx.x == 0) ssum[0] = t;
    }
    __syncthreads();
    float scale = 32.0f / fmaxf(sqrtf(ssum[0]), 1e-12f);
    float4 w = make_float4(v.x * scale, v.y * scale, v.z * scale, v.w * scale);
    ((float4*)(o + (size_t)row * DMODEL))[threadIdx.x] = w;
    __half2 h01 = __halves2half2(__float2half_rn(w.x), __float2half_rn(w.y));
    __half2 h23 = __halves2half2(__float2half_rn(w.z), __float2half_rn(w.w));
    ((uint2*)(oh + (size_t)row * DMODEL))[threadIdx.x] =
        make_uint2(*(uint32_t*)&h01, *(uint32_t*)&h23);
}

// ---------------- split-K SIMT GEMM for skinny x_proj (exact fp32) ----------------
__global__ void __launch_bounds__(256) gemm_sk(
    const float* __restrict__ A, int lda,
    const float* __restrict__ W, int ldw,
    float* __restrict__ Cpart, int ldc,
    int M, int N, int kchunk)
{
    int koff = blockIdx.z * kchunk;
    float* C = Cpart + (size_t)blockIdx.z * M * ldc;
    __shared__ float As[16][68];
    __shared__ float Bs[16][68];
    int tid = threadIdx.x;
    int m0 = blockIdx.x * 64, n0 = blockIdx.y * 64;
    int tx = tid & 15, ty = tid >> 4;
    int lr = tid >> 2;
    int lk = (tid & 3) << 2;
    int am = m0 + lr;
    int wn = n0 + lr;
    bool a_ok = am < M;
    bool w_ok = wn < N;
    const float* Arow = A + (size_t)(a_ok ? am : 0) * lda + koff;
    const float* Wrow = W + (size_t)(w_ok ? wn : 0) * ldw + koff;
    float acc[4][4] = {};
    for (int k0 = 0; k0 < kchunk; k0 += 16) {
        float4 av = a_ok ? *(const float4*)(Arow + k0 + lk) : make_float4(0, 0, 0, 0);
        float4 wv = w_ok ? *(const float4*)(Wrow + k0 + lk) : make_float4(0, 0, 0, 0);
        __syncthreads();
        As[lk][lr] = av.x; As[lk + 1][lr] = av.y; As[lk + 2][lr] = av.z; As[lk + 3][lr] = av.w;
        Bs[lk][lr] = wv.x; Bs[lk + 1][lr] = wv.y; Bs[lk + 2][lr] = wv.z; Bs[lk + 3][lr] = wv.w;
        __syncthreads();
        #pragma unroll
        for (int k = 0; k < 16; k++) {
            float a[4], b[4];
            #pragma unroll
            for (int i = 0; i < 4; i++) a[i] = As[k][ty * 4 + i];
            #pragma unroll
            for (int j = 0; j < 4; j++) b[j] = Bs[k][tx * 4 + j];
            #pragma unroll
            for (int i = 0; i < 4; i++)
                #pragma unroll
                for (int j = 0; j < 4; j++)
                    acc[i][j] += a[i] * b[j];
        }
    }
    #pragma unroll
    for (int i = 0; i < 4; i++) {
        int m = m0 + ty * 4 + i;
        if (m >= M) continue;
        #pragma unroll
        for (int j = 0; j < 4; j++) {
            int n = n0 + tx * 4 + j;
            if (n >= N) continue;
            C[(size_t)m * ldc + n] = acc[i][j];
        }
    }
}

__global__ void reduce_sk(const float* __restrict__ p, float* __restrict__ o,
                          __half* __restrict__ oh, int n)
{
    int i = blockIdx.x * 256 + threadIdx.x;
    if (i >= n) return;
    float s = 0.f;
    #pragma unroll
    for (int j = 0; j < SPLITK; j++) s += p[i + (size_t)j * n];
    o[i] = s;
    oh[i] = __float2half_rn(s);
}

// ---------------- causal depthwise conv(4) + silu ----------------
__global__ void conv_silu(const float* __restrict__ xr, const float* __restrict__ cw,
                          const float* __restrict__ cb, float* __restrict__ u)
{
    int idx = blockIdx.x * 256 + threadIdx.x;
    int t = idx >> 11, d = idx & (DINNER - 1);
    float w0 = cw[d * 4], w1 = cw[d * 4 + 1], w2 = cw[d * 4 + 2], w3 = cw[d * 4 + 3];
    float s = cb[d];
    const float* col = xr + d;
    if (t >= 3) s += col[(size_t)(t - 3) * (2 * DINNER)] * w0;
    if (t >= 2) s += col[(size_t)(t - 2) * (2 * DINNER)] * w1;
    if (t >= 1) s += col[(size_t)(t - 1) * (2 * DINNER)] * w2;
    s += col[(size_t)t * (2 * DINNER)] * w3;
    u[idx] = s / (1.f + __expf(-s));
}

// ---------------- selective scan (fp16 y out) ----------------
__global__ void scan_kernel(const float* __restrict__ delta,
                            const float* __restrict__ u,
                            const float* __restrict__ xdbl,
                            const float* __restrict__ A_log,
                            const float* __restrict__ Dvec,
                            const float* __restrict__ xr,
                            __half* __restrict__ yh)
{
    int lane16 = threadIdx.x & 15;
    int ch = threadIdx.x >> 4;
    int d = blockIdx.x * 8 + ch;
    float A = -__expf(A_log[d * DSTATE + lane16]);
    float Dd = Dvec[d];
    float h = 0.f;
    __shared__ float sB[32][16], sC[32][16], sdl[32][8], su[32][8], sre[32][8];
    for (int t0 = 0; t0 < LSEQ; t0 += 32) {
        __syncthreads();
        for (int i = threadIdx.x; i < 512; i += 128) {
            int tt = i >> 4, n = i & 15;
            const float* xb = xdbl + (size_t)(t0 + tt) * XDBL;
            sB[tt][n] = xb[DTRANK + n];
            sC[tt][n] = xb[DTRANK + DSTATE + n];
        }
        for (int i = threadIdx.x; i < 256; i += 128) {
            int tt = i >> 3, c = i & 7;
            int dd = blockIdx.x * 8 + c;
            size_t off = (size_t)(t0 + tt) * DINNER + dd;
            sdl[tt][c] = delta[off];
            su[tt][c]  = u[off];
            sre[tt][c] = xr[(size_t)(t0 + tt) * (2 * DINNER) + DINNER + dd];
        }
        __syncthreads();
        for (int tt = 0; tt < 32; tt++) {
            float dl = sdl[tt][ch];
            float uu = su[tt][ch];
            float dA = __expf(dl * A);
            h = dA * h + dl * sB[tt][lane16] * uu;
            float p = h * sC[tt][lane16];
            #pragma unroll
            for (int o = 8; o; o >>= 1) p += __shfl_xor_sync(0xffffffffu, p, o, 16);
            if (lane16 == 0) {
                float yv = p + uu * Dd;
                float r = sre[tt][ch];
                yv *= r / (1.f + __expf(-r));
                yh[(size_t)(t0 + tt) * DINNER + d] = __float2half_rn(yv);
            }
        }
    }
}

// ---------------- gating: GEMV + softmax + top-2 ----------------
__global__ void gate_topk(const float* __restrict__ X, const float* __restrict__ gw,
                          int* __restrict__ te, float* __restrict__ tv)
{
    __shared__ float sg[NEXP * DMODEL];
    for (int i = threadIdx.x; i < NEXP * DMODEL; i += 128) sg[i] = gw[i];
    __syncthreads();
    int warp = threadIdx.x >> 5, lane = threadIdx.x & 31;
    int t = blockIdx.x * 4 + warp;
    const float* xp = X + (size_t)t * DMODEL;
    float acc[NEXP] = {};
    for (int k = lane; k < DMODEL; k += 32) {
        float xv = xp[k];
        #pragma unroll
        for (int e = 0; e < NEXP; e++) acc[e] += xv * sg[e * DMODEL + k];
    }
    #pragma unroll
    for (int e = 0; e < NEXP; e++)
        #pragma unroll
        for (int o = 16; o; o >>= 1) acc[e] += __shfl_xor_sync(0xffffffffu, acc[e], o);
    if (lane == 0) {
        float m = acc[0];
        #pragma unroll
        for (int e = 1; e < NEXP; e++) m = fmaxf(m, acc[e]);
        float g[NEXP];
        #pragma unroll
        for (int e = 0; e < NEXP; e++) g[e] = __expf(acc[e] - m);
        int i0 = 0;
        #pragma unroll
        for (int e = 1; e < NEXP; e++) if (g[e] > g[i0]) i0 = e;
        int i1 = (i0 == 0) ? 1 : 0;
        #pragma unroll
        for (int e = 0; e < NEXP; e++) if (e != i0 && g[e] > g[i1]) i1 = e;
        float inv = 1.f / (g[i0] + g[i1]);
        te[t * 2] = i0; te[t * 2 + 1] = i1;
        tv[t * 2] = g[i0] * inv; tv[t * 2 + 1] = g[i1] * inv;
    }
}

// ---------------- routing ----------------
__global__ void route_zero(int* cnt, int* cur)
{
    if (threadIdx.x < NEXP) { cnt[threadIdx.x] = 0; cur[threadIdx.x] = 0; }
}
__global__ void route_count(const int* __restrict__ te, int* cnt)
{
    int t = blockIdx.x * 256 + threadIdx.x;
    atomicAdd(&cnt[te[t * 2]], 1);
    atomicAdd(&cnt[te[t * 2 + 1]], 1);
}
__global__ void route_offsets(const int* __restrict__ cnt, int* off)
{
    int s = 0;
    for (int e = 0; e < NEXP; e++) { off[e] = s; s += cnt[e]; }
    off[NEXP] = s;
}
__global__ void route_scatter(const int* __restrict__ te, const float* __restrict__ tv,
                              const int* __restrict__ off, int* cur,
                              int* ptok, float* pw, int* tok_pair)
{
    int t = blockIdx.x * 256 + threadIdx.x;
    #pragma unroll
    for (int k = 0; k < 2; k++) {
        int e = te[t * 2 + k];
        int pos = atomicAdd(&cur[e], 1);
        int p = off[e] + pos;
        ptok[p] = t;
        pw[p] = tv[t * 2 + k];
        tok_pair[t * 2 + k] = p;
    }
}

// ---------------- final combine ----------------
__global__ void moe_combine(const float* __restrict__ x, const float* __restrict__ y2,
                            const int* __restrict__ tok_pair, const float* __restrict__ pw,
                            float* __restrict__ out)
{
    int i = blockIdx.x * 256 + threadIdx.x;
    int t = i >> 10, n = i & (DMODEL - 1);
    int p0 = tok_pair[t * 2], p1 = tok_pair[t * 2 + 1];
    out[i] = x[i] + pw[p0] * y2[(size_t)p0 * DMODEL + n]
                  + pw[p1] * y2[(size_t)p1 * DMODEL + n];
}

// ---------------- launch ----------------
extern "C" void kernel_launch(void* const* d_in, const int* in_sizes, int n_in,
                              void* d_out, int out_size)
{
    (void)in_sizes; (void)n_in; (void)out_size;
    const float* x          = (const float*)d_in[0];
    const float* in_proj_w  = (const float*)d_in[1];
    const float* conv_w     = (const float*)d_in[2];
    const float* conv_b     = (const float*)d_in[3];
    const float* x_proj_w   = (const float*)d_in[4];
    const float* dt_proj_w  = (const float*)d_in[5];
    const float* dt_proj_b  = (const float*)d_in[6];
    const float* A_log      = (const float*)d_in[7];
    const float* Dvec       = (const float*)d_in[8];
    const float* out_proj_w = (const float*)d_in[9];
    const float* gate_w     = (const float*)d_in[10];
    const float* w1         = (const float*)d_in[11];
    const float* w2         = (const float*)d_in[12];
    float* out = (float*)d_out;

    float *p_xn, *p_xr, *p_u, *p_xdbl, *p_xp, *p_delta, *p_xm2, *p_xm2n, *p_y2, *p_tv, *p_pw;
    int *p_te, *p_cnt, *p_cur, *p_off, *p_ptok, *p_tp;
    cudaGetSymbolAddress((void**)&p_xn, g_xn);
    cudaGetSymbolAddress((void**)&p_xr, g_xr);
    cudaGetSymbolAddress((void**)&p_u, g_u);
    cudaGetSymbolAddress((void**)&p_xdbl, g_xdbl);
    cudaGetSymbolAddress((void**)&p_xp, g_xp);
    cudaGetSymbolAddress((void**)&p_delta, g_delta);
    cudaGetSymbolAddress((void**)&p_xm2, g_xm2);
    cudaGetSymbolAddress((void**)&p_xm2n, g_xm2n);
    cudaGetSymbolAddress((void**)&p_y2, g_y2);
    cudaGetSymbolAddress((void**)&p_te, g_top_e);
    cudaGetSymbolAddress((void**)&p_tv, g_top_v);
    cudaGetSymbolAddress((void**)&p_cnt, g_cnt);
    cudaGetSymbolAddress((void**)&p_cur, g_cur);
    cudaGetSymbolAddress((void**)&p_off, g_off);
    cudaGetSymbolAddress((void**)&p_ptok, g_ptok);
    cudaGetSymbolAddress((void**)&p_pw, g_pw);
    cudaGetSymbolAddress((void**)&p_tp, g_tok_pair);

    __half *xnh, *xdh, *yh, *x2h, *hh, *wih, *wdh, *woh, *w1h, *w2h;
    cudaGetSymbolAddress((void**)&xnh, h_xn);
    cudaGetSymbolAddress((void**)&xdh, h_xd);
    cudaGetSymbolAddress((void**)&yh,  h_y);
    cudaGetSymbolAddress((void**)&x2h, h_x2);
    cudaGetSymbolAddress((void**)&hh,  h_h);
    cudaGetSymbolAddress((void**)&wih, h_wi);
    cudaGetSymbolAddress((void**)&wdh, h_wd);
    cudaGetSymbolAddress((void**)&woh, h_wo);
    cudaGetSymbolAddress((void**)&w1h, h_w1);
    cudaGetSymbolAddress((void**)&w2h, h_w2);

    const int SMEM = 2 * STG_B;   // 32 KB
    cudaFuncSetAttribute(hgemm<0, 0>, cudaFuncAttributeMaxDynamicSharedMemorySize, SMEM);
    cudaFuncSetAttribute(hgemm<2, 0>, cudaFuncAttributeMaxDynamicSharedMemorySize, SMEM);
    cudaFuncSetAttribute(hgemm<3, 0>, cudaFuncAttributeMaxDynamicSharedMemorySize, SMEM);
    cudaFuncSetAttribute(hgemm<1, 1>, cudaFuncAttributeMaxDynamicSharedMemorySize, SMEM);
    cudaFuncSetAttribute(hgemm<0, 2>, cudaFuncAttributeMaxDynamicSharedMemorySize, SMEM);

    // 0. convert weights to fp16
    conv_h<<<(2 * DINNER * DMODEL / 4 + 255) / 256, 256>>>((const float4*)in_proj_w, (uint2*)wih, 2 * DINNER * DMODEL / 4);
    conv_h<<<(DINNER * DTRANK / 4 + 255) / 256, 256>>>((const float4*)dt_proj_w, (uint2*)wdh, DINNER * DTRANK / 4);
    conv_h<<<(DMODEL * DINNER / 4 + 255) / 256, 256>>>((const float4*)out_proj_w, (uint2*)woh, DMODEL * DINNER / 4);
    conv_h<<<(int)((size_t)NEXP * HIDDEN * DMODEL / 4 + 255) / 256, 256>>>((const float4*)w1, (uint2*)w1h, NEXP * HIDDEN * DMODEL / 4);
    conv_h<<<(int)((size_t)NEXP * DMODEL * HIDDEN / 4 + 255) / 256, 256>>>((const float4*)w2, (uint2*)w2h, NEXP * DMODEL * HIDDEN / 4);

    // 1. xn = rmsnorm(x)
    rmsnorm_h<<<LSEQ, 256>>>(x, p_xn, xnh);
    // 2. xr = xn @ in_proj^T (2048x4096, K=1024)
    hgemm<0, 0><<<dim3(16, 32), 256, SMEM>>>(xnh, DMODEL, wih, DMODEL,
                                             p_xr, 2 * DINNER, LSEQ, 2 * DINNER,
                                             nullptr, nullptr, 0, nullptr, nullptr, nullptr);
    // 3. conv + silu
    conv_silu<<<(LSEQ * DINNER) / 256, 256>>>(p_xr, conv_w, conv_b, p_u);
    // 4. x_dbl = u @ x_proj^T (2048x96, K=2048) split-K exact fp32
    gemm_sk<<<dim3(32, 2, SPLITK), 256>>>(p_u, DINNER, x_proj_w, DINNER,
                                          p_xp, XDBL, LSEQ, XDBL, DINNER / SPLITK);
    reduce_sk<<<(LSEQ * XDBL + 255) / 256, 256>>>(p_xp, p_xdbl, xdh, LSEQ * XDBL);
    // 5. delta = softplus(dt @ dt_proj^T + b) (2048x2048, K=64)
    hgemm<3, 0><<<dim3(16, 16), 256, SMEM>>>(xdh, XDBL, wdh, DTRANK,
                                             p_delta, DINNER, LSEQ, DINNER,
                                             dt_proj_b, nullptr, 0, nullptr, nullptr, nullptr);
    // 6. selective scan -> y fp16
    scan_kernel<<<DINNER / 8, 128>>>(p_delta, p_u, p_xdbl, A_log, Dvec, p_xr, yh);
    // 7. xm2 = y @ out_proj^T + xn (2048x1024, K=2048)
    hgemm<2, 0><<<dim3(16, 8), 256, SMEM>>>(yh, DINNER, woh, DINNER,
                                            p_xm2, DMODEL, LSEQ, DMODEL,
                                            nullptr, p_xn, DMODEL, nullptr, nullptr, nullptr);
    // 8. xm2n = rmsnorm(xm2)
    rmsnorm_h<<<LSEQ, 256>>>(p_xm2, p_xm2n, x2h);
    // 9. gating + routing
    gate_topk<<<LSEQ / 4, 128>>>(p_xm2n, gate_w, p_te, p_tv);
    route_zero<<<1, 32>>>(p_cnt, p_cur);
    route_count<<<LSEQ / 256, 256>>>(p_te, p_cnt);
    route_offsets<<<1, 1>>>(p_cnt, p_off);
    route_scatter<<<LSEQ / 256, 256>>>(p_te, p_tv, p_off, p_cur, p_ptok, p_pw, p_tp);
    // 10. expert GEMMs
    hgemm<1, 1><<<dim3(32, 32, NEXP), 256, SMEM>>>(x2h, DMODEL, w1h, DMODEL,
                                                   nullptr, HIDDEN, 0, HIDDEN,
                                                   nullptr, nullptr, 0, p_off, p_ptok, hh);
    hgemm<0, 2><<<dim3(32, 8, NEXP), 256, SMEM>>>(hh, HIDDEN, w2h, HIDDEN,
                                                  p_y2, DMODEL, 0, DMODEL,
                                                  nullptr, nullptr, 0, p_off, nullptr, nullptr);
    moe_combine<<<(LSEQ * DMODEL) / 256, 256>>>(x, p_y2, p_tp, p_pw, out);
}

// round 9
// speedup vs baseline: 2.8991x; 1.0068x over previous
#include <cuda_runtime.h>
#include <cuda_fp16.h>
#include <math.h>
#include <stdint.h>

// ---------------- problem constants ----------------
#define LSEQ   2048
#define DMODEL 1024
#define DINNER 2048
#define DSTATE 16
#define DTRANK 64
#define XDBL   96
#define NEXP   8
#define HIDDEN 4096
#define NPAIR  4096
#define SPLITK 8

// ---------------- fp32 scratch ----------------
__device__ float g_xn   [LSEQ * DMODEL];
__device__ float g_xr   [LSEQ * 2 * DINNER];
__device__ float g_u    [LSEQ * DINNER];
__device__ float g_xdbl [LSEQ * XDBL];
__device__ float g_xp   [SPLITK * LSEQ * XDBL];
__device__ float g_delta[LSEQ * DINNER];
__device__ float g_xm2  [LSEQ * DMODEL];
__device__ float g_xm2n [LSEQ * DMODEL];
__device__ float g_y2   [(size_t)NPAIR * DMODEL];
__device__ int   g_top_e[LSEQ * 2];
__device__ float g_top_v[LSEQ * 2];
__device__ int   g_cnt[NEXP];
__device__ int   g_cur[NEXP];
__device__ int   g_off[NEXP + 1];
__device__ int   g_ptok[NPAIR];
__device__ float g_pw  [NPAIR];
__device__ int   g_tok_pair[LSEQ * 2];

// ---------------- fp16 scratch ----------------
__device__ __align__(16) __half h_xn [LSEQ * DMODEL];
__device__ __align__(16) __half h_xd [LSEQ * XDBL];
__device__ __align__(16) __half h_y  [LSEQ * DINNER];
__device__ __align__(16) __half h_x2 [LSEQ * DMODEL];
__device__ __align__(16) __half h_h  [(size_t)NPAIR * HIDDEN];
__device__ __align__(16) __half h_wi [2 * DINNER * DMODEL];
__device__ __align__(16) __half h_wd [DINNER * DTRANK];
__device__ __align__(16) __half h_wo [DMODEL * DINNER];
__device__ __align__(16) __half h_w1 [(size_t)NEXP * HIDDEN * DMODEL];
__device__ __align__(16) __half h_w2 [(size_t)NEXP * DMODEL * HIDDEN];

// ---------------- helpers ----------------
__device__ __forceinline__ void cpa16(uint32_t dst, const void* src)
{
    asm volatile("cp.async.cg.shared.global [%0], [%1], 16;" :: "r"(dst), "l"(src));
}

__device__ __forceinline__ void ldsm4(uint32_t* r, uint32_t a)
{
    asm volatile("ldmatrix.sync.aligned.m8n8.x4.shared.b16 {%0,%1,%2,%3}, [%4];"
                 : "=r"(r[0]), "=r"(r[1]), "=r"(r[2]), "=r"(r[3]) : "r"(a));
}

__device__ __forceinline__ void hmma(float* d, const uint32_t* a, const uint32_t* b)
{
    asm volatile(
        "mma.sync.aligned.m16n8k16.row.col.f32.f16.f16.f32 "
        "{%0,%1,%2,%3},{%4,%5,%6,%7},{%8,%9},{%0,%1,%2,%3};\n"
        : "+f"(d[0]), "+f"(d[1]), "+f"(d[2]), "+f"(d[3])
        : "r"(a[0]), "r"(a[1]), "r"(a[2]), "r"(a[3]), "r"(b[0]), "r"(b[1]));
}

// ---------------- weight convert: fp32 -> fp16 ----------------
__global__ void conv_h(const float4* __restrict__ src, uint2* __restrict__ dst, int n4)
{
    int i = blockIdx.x * 256 + threadIdx.x;
    if (i >= n4) return;
    float4 v = src[i];
    __half2 h01 = __halves2half2(__float2half_rn(v.x), __float2half_rn(v.y));
    __half2 h23 = __halves2half2(__float2half_rn(v.z), __float2half_rn(v.w));
    dst[i] = make_uint2(*(uint32_t*)&h01, *(uint32_t*)&h23);
}

// ---------------- fp16 tensor GEMM: C = epi(A @ W^T) ----------------
// A: (M,K) fp16 row-major stride lda. W: (N,K) fp16 stride K.
// CTA tile 128x128, k-stage 32, 3-stage cp.async pipeline (1 sync/iter).
// 8 warps: 2m x 4n, warp tile 64x32.
// EPI: 0 store fp32, 1 gelu->fp16, 2 +addsrc fp32, 3 softplus(+bias) fp32
// MODE: 0 plain, 1 gather A rows via ptok + per-expert W, 2 contiguous expert rows
#define STG_B 16384
#define NSTG  3
template<int EPI, int MODE>
__global__ void __launch_bounds__(256, 2) hgemm(
    const __half* __restrict__ Aq, int lda,
    const __half* __restrict__ Wq, int K,
    float* __restrict__ C, int ldc, int M, int N,
    const float* __restrict__ bias, const float* __restrict__ addsrc, int ldadd,
    const int* __restrict__ off, const int* __restrict__ ptok,
    __half* __restrict__ Ch)
{
    extern __shared__ __align__(16) uint8_t smem[];
    int base = 0, rows = M;
    const __half* W = Wq;
    if (MODE != 0) {
        int e = blockIdx.z;
        base = off[e];
        rows = off[e + 1] - base;
        W += (size_t)e * (size_t)N * K;
    }
    int m0 = blockIdx.x * 128;
    if (m0 >= rows) return;
    int n0 = blockIdx.y * 128;

    int tid = threadIdx.x;
    int wid = tid >> 5, lane = tid & 31;
    int lr = lane >> 2, lc = lane & 3;
    int warp_m = wid >> 2, warp_n = wid & 3;

    // ---- global load mapping: 2 rows per thread per tile, 16B segment qg ----
    int qg = tid & 3;
    int ar = tid >> 2;                 // 0..63
    int rA0 = m0 + ar, rA1 = rA0 + 64;
    int c0 = rA0 < rows ? rA0 : rows - 1;
    int c1 = rA1 < rows ? rA1 : rows - 1;
    int gA0, gA1;
    if (MODE == 1)      { gA0 = ptok[base + c0]; gA1 = ptok[base + c1]; }
    else if (MODE == 2) { gA0 = base + c0;       gA1 = base + c1; }
    else                { gA0 = c0;              gA1 = c1; }

    const __half* pA0 = Aq + (size_t)gA0 * lda + qg * 8;
    const __half* pA1 = Aq + (size_t)gA1 * lda + qg * 8;
    const __half* pB0 = W + (size_t)(n0 + ar) * K + qg * 8;
    const __half* pB1 = W + (size_t)(n0 + ar + 64) * K + qg * 8;

    uint32_t sb0 = (uint32_t)__cvta_generic_to_shared(smem);
    int dst0 = ar * 64 + ((qg ^ ((ar >> 1) & 3)) << 4);
    int dst1 = dst0 + 4096;

    // ---- per-lane ldmatrix addresses (byte offsets within stage) ----
    int rA = warp_m * 64 + (lane & 15);
    int swzA = (rA >> 1) & 3;
    int aoff0 = rA * 64 + ((((lane >> 4)) ^ swzA) << 4);
    int aoff1 = rA * 64 + (((2 + (lane >> 4)) ^ swzA) << 4);
    int rB = warp_n * 32 + (lane & 7) + ((lane >> 4) << 3);
    int swzB = (rB >> 1) & 3;
    int boff0 = rB * 64 + ((((lane >> 3) & 1) ^ swzB) << 4);
    int boff1 = rB * 64 + (((2 + ((lane >> 3) & 1)) ^ swzB) << 4);

    float acc[4][4][4];
    #pragma unroll
    for (int i = 0; i < 4; i++)
        #pragma unroll
        for (int j = 0; j < 4; j++)
            #pragma unroll
            for (int r = 0; r < 4; r++) acc[i][j][r] = 0.f;

    int nt = K >> 5;
    // prologue: stages 0 and 1
    {
        cpa16(sb0 + 0    + dst0, pA0);
        cpa16(sb0 + 0    + dst1, pA1);
        cpa16(sb0 + 8192 + dst0, pB0);
        cpa16(sb0 + 8192 + dst1, pB1);
        asm volatile("cp.async.commit_group;");
        if (nt > 1) {
            uint32_t s = sb0 + STG_B;
            cpa16(s + 0    + dst0, pA0 + 32);
            cpa16(s + 0    + dst1, pA1 + 32);
            cpa16(s + 8192 + dst0, pB0 + 32);
            cpa16(s + 8192 + dst1, pB1 + 32);
        }
        asm volatile("cp.async.commit_group;");
    }
    int buf = 0;
    for (int t = 0; t < nt; t++) {
        asm volatile("cp.async.wait_group 1;");   // stage t complete (t+1 may fly)
        __syncthreads();                           // visibility + frees buf (t+2)%3
        if (t + 2 < nt) {
            int kc = (t + 2) << 5;
            int nb = buf + 2; if (nb >= NSTG) nb -= NSTG;
            uint32_t s = sb0 + nb * STG_B;
            cpa16(s + 0    + dst0, pA0 + kc);
            cpa16(s + 0    + dst1, pA1 + kc);
            cpa16(s + 8192 + dst0, pB0 + kc);
            cpa16(s + 8192 + dst1, pB1 + kc);
        }
        asm volatile("cp.async.commit_group;");

        uint32_t S = sb0 + buf * STG_B;
        #pragma unroll
        for (int sub = 0; sub < 2; sub++) {
            uint32_t aadr = S + (sub ? aoff1 : aoff0);
            uint32_t badr = S + 8192 + (sub ? boff1 : boff0);
            uint32_t ah[4][4];
            #pragma unroll
            for (int im = 0; im < 4; im++) ldsm4(ah[im], aadr + im * 1024);
            uint32_t b0[4], b1[4];
            ldsm4(b0, badr);
            ldsm4(b1, badr + 1024);
            #pragma unroll
            for (int im = 0; im < 4; im++) {
                hmma(acc[im][0], ah[im], b0);
                hmma(acc[im][1], ah[im], b0 + 2);
                hmma(acc[im][2], ah[im], b1);
                hmma(acc[im][3], ah[im], b1 + 2);
            }
        }
        if (++buf == NSTG) buf = 0;
    }

    // ---- epilogue ----
    #pragma unroll
    for (int im = 0; im < 4; im++) {
        #pragma unroll
        for (int half = 0; half < 2; half++) {
            int m = m0 + warp_m * 64 + im * 16 + lr + half * 8;
            if (m >= rows) continue;
            size_t crow = (size_t)(base + m) * (size_t)ldc;
            if (MODE == 0) crow = (size_t)m * ldc;
            #pragma unroll
            for (int in = 0; in < 4; in++) {
                int n = n0 + warp_n * 32 + in * 8 + lc * 2;
                float v0 = acc[im][in][half * 2];
                float v1 = acc[im][in][half * 2 + 1];
                if (EPI == 1) {
                    v0 = 0.5f * v0 * (1.0f + erff(v0 * 0.70710678118654752f));
                    v1 = 0.5f * v1 * (1.0f + erff(v1 * 0.70710678118654752f));
                    __half2 hv = __halves2half2(__float2half_rn(v0), __float2half_rn(v1));
                    *(__half2*)(Ch + crow + n) = hv;
                } else {
                    if (EPI == 2) {
                        v0 += addsrc[(size_t)m * ldadd + n];
                        v1 += addsrc[(size_t)m * ldadd + n + 1];
                    } else if (EPI == 3) {
                        float z0 = v0 + bias[n], z1 = v1 + bias[n + 1];
                        v0 = (z0 > 20.f) ? z0 : log1pf(__expf(z0));
                        v1 = (z1 > 20.f) ? z1 : log1pf(__expf(z1));
                    }
                    *(float2*)(C + crow + n) = make_float2(v0, v1);
                }
            }
        }
    }
}

// ---------------- rmsnorm (writes fp32 + fp16) ----------------
__global__ void rmsnorm_h(const float* __restrict__ x, float* __restrict__ o,
                          __half* __restrict__ oh)
{
    int row = blockIdx.x;
    const float4* xp = (const float4*)(x + (size_t)row * DMODEL);
    float4 v = xp[threadIdx.x];
    float s = v.x * v.x + v.y * v.y + v.z * v.z + v.w * v.w;
    __shared__ float ssum[8];
    #pragma unroll
    for (int off = 16; off; off >>= 1) s += __shfl_xor_sync(0xffffffffu, s, off);
    if ((threadIdx.x & 31) == 0) ssum[threadIdx.x >> 5] = s;
    __syncthreads();
    if (threadIdx.x < 8) {
        float t = ssum[threadIdx.x];
        #pragma unroll
        for (int off = 4; off; off >>= 1) t += __shfl_xor_sync(0xffu, t, off);
        if (threadIdx.x == 0) ssum[0] = t;
    }
    __syncthreads();
    float scale = 32.0f / fmaxf(sqrtf(ssum[0]), 1e-12f);
    float4 w = make_float4(v.x * scale, v.y * scale, v.z * scale, v.w * scale);
    ((float4*)(o + (size_t)row * DMODEL))[threadIdx.x] = w;
    __half2 h01 = __halves2half2(__float2half_rn(w.x), __float2half_rn(w.y));
    __half2 h23 = __halves2half2(__float2half_rn(w.z), __float2half_rn(w.w));
    ((uint2*)(oh + (size_t)row * DMODEL))[threadIdx.x] =
        make_uint2(*(uint32_t*)&h01, *(uint32_t*)&h23);
}

// ---------------- split-K SIMT GEMM for skinny x_proj (exact fp32) ----------------
__global__ void __launch_bounds__(256) gemm_sk(
    const float* __restrict__ A, int lda,
    const float* __restrict__ W, int ldw,
    float* __restrict__ Cpart, int ldc,
    int M, int N, int kchunk)
{
    int koff = blockIdx.z * kchunk;
    float* C = Cpart + (size_t)blockIdx.z * M * ldc;
    __shared__ float As[16][68];
    __shared__ float Bs[16][68];
    int tid = threadIdx.x;
    int m0 = blockIdx.x * 64, n0 = blockIdx.y * 64;
    int tx = tid & 15, ty = tid >> 4;
    int lr = tid >> 2;
    int lk = (tid & 3) << 2;
    int am = m0 + lr;
    int wn = n0 + lr;
    bool a_ok = am < M;
    bool w_ok = wn < N;
    const float* Arow = A + (size_t)(a_ok ? am : 0) * lda + koff;
    const float* Wrow = W + (size_t)(w_ok ? wn : 0) * ldw + koff;
    float acc[4][4] = {};
    for (int k0 = 0; k0 < kchunk; k0 += 16) {
        float4 av = a_ok ? *(const float4*)(Arow + k0 + lk) : make_float4(0, 0, 0, 0);
        float4 wv = w_ok ? *(const float4*)(Wrow + k0 + lk) : make_float4(0, 0, 0, 0);
        __syncthreads();
        As[lk][lr] = av.x; As[lk + 1][lr] = av.y; As[lk + 2][lr] = av.z; As[lk + 3][lr] = av.w;
        Bs[lk][lr] = wv.x; Bs[lk + 1][lr] = wv.y; Bs[lk + 2][lr] = wv.z; Bs[lk + 3][lr] = wv.w;
        __syncthreads();
        #pragma unroll
        for (int k = 0; k < 16; k++) {
            float a[4], b[4];
            #pragma unroll
            for (int i = 0; i < 4; i++) a[i] = As[k][ty * 4 + i];
            #pragma unroll
            for (int j = 0; j < 4; j++) b[j] = Bs[k][tx * 4 + j];
            #pragma unroll
            for (int i = 0; i < 4; i++)
                #pragma unroll
                for (int j = 0; j < 4; j++)
                    acc[i][j] += a[i] * b[j];
        }
    }
    #pragma unroll
    for (int i = 0; i < 4; i++) {
        int m = m0 + ty * 4 + i;
        if (m >= M) continue;
        #pragma unroll
        for (int j = 0; j < 4; j++) {
            int n = n0 + tx * 4 + j;
            if (n >= N) continue;
            C[(size_t)m * ldc + n] = acc[i][j];
        }
    }
}

__global__ void reduce_sk(const float* __restrict__ p, float* __restrict__ o,
                          __half* __restrict__ oh, int n)
{
    int i = blockIdx.x * 256 + threadIdx.x;
    if (i >= n) return;
    float s = 0.f;
    #pragma unroll
    for (int j = 0; j < SPLITK; j++) s += p[i + (size_t)j * n];
    o[i] = s;
    oh[i] = __float2half_rn(s);
}

// ---------------- causal depthwise conv(4) + silu ----------------
__global__ void conv_silu(const float* __restrict__ xr, const float* __restrict__ cw,
                          const float* __restrict__ cb, float* __restrict__ u)
{
    int idx = blockIdx.x * 256 + threadIdx.x;
    int t = idx >> 11, d = idx & (DINNER - 1);
    float w0 = cw[d * 4], w1 = cw[d * 4 + 1], w2 = cw[d * 4 + 2], w3 = cw[d * 4 + 3];
    float s = cb[d];
    const float* col = xr + d;
    if (t >= 3) s += col[(size_t)(t - 3) * (2 * DINNER)] * w0;
    if (t >= 2) s += col[(size_t)(t - 2) * (2 * DINNER)] * w1;
    if (t >= 1) s += col[(size_t)(t - 1) * (2 * DINNER)] * w2;
    s += col[(size_t)t * (2 * DINNER)] * w3;
    u[idx] = s / (1.f + __expf(-s));
}

// ---------------- selective scan (fp16 y out) ----------------
__global__ void scan_kernel(const float* __restrict__ delta,
                            const float* __restrict__ u,
                            const float* __restrict__ xdbl,
                            const float* __restrict__ A_log,
                            const float* __restrict__ Dvec,
                            const float* __restrict__ xr,
                            __half* __restrict__ yh)
{
    int lane16 = threadIdx.x & 15;
    int ch = threadIdx.x >> 4;
    int d = blockIdx.x * 8 + ch;
    float A = -__expf(A_log[d * DSTATE + lane16]);
    float Dd = Dvec[d];
    float h = 0.f;
    __shared__ float sB[32][16], sC[32][16], sdl[32][8], su[32][8], sre[32][8];
    for (int t0 = 0; t0 < LSEQ; t0 += 32) {
        __syncthreads();
        for (int i = threadIdx.x; i < 512; i += 128) {
            int tt = i >> 4, n = i & 15;
            const float* xb = xdbl + (size_t)(t0 + tt) * XDBL;
            sB[tt][n] = xb[DTRANK + n];
            sC[tt][n] = xb[DTRANK + DSTATE + n];
        }
        for (int i = threadIdx.x; i < 256; i += 128) {
            int tt = i >> 3, c = i & 7;
            int dd = blockIdx.x * 8 + c;
            size_t off = (size_t)(t0 + tt) * DINNER + dd;
            sdl[tt][c] = delta[off];
            su[tt][c]  = u[off];
            sre[tt][c] = xr[(size_t)(t0 + tt) * (2 * DINNER) + DINNER + dd];
        }
        __syncthreads();
        for (int tt = 0; tt < 32; tt++) {
            float dl = sdl[tt][ch];
            float uu = su[tt][ch];
            float dA = __expf(dl * A);
            h = dA * h + dl * sB[tt][lane16] * uu;
            float p = h * sC[tt][lane16];
            #pragma unroll
            for (int o = 8; o; o >>= 1) p += __shfl_xor_sync(0xffffffffu, p, o, 16);
            if (lane16 == 0) {
                float yv = p + uu * Dd;
                float r = sre[tt][ch];
                yv *= r / (1.f + __expf(-r));
                yh[(size_t)(t0 + tt) * DINNER + d] = __float2half_rn(yv);
            }
        }
    }
}

// ---------------- gating: GEMV + softmax + top-2 ----------------
__global__ void gate_topk(const float* __restrict__ X, const float* __restrict__ gw,
                          int* __restrict__ te, float* __restrict__ tv)
{
    __shared__ float sg[NEXP * DMODEL];
    for (int i = threadIdx.x; i < NEXP * DMODEL; i += 128) sg[i] = gw[i];
    __syncthreads();
    int warp = threadIdx.x >> 5, lane = threadIdx.x & 31;
    int t = blockIdx.x * 4 + warp;
    const float* xp = X + (size_t)t * DMODEL;
    float acc[NEXP] = {};
    for (int k = lane; k < DMODEL; k += 32) {
        float xv = xp[k];
        #pragma unroll
        for (int e = 0; e < NEXP; e++) acc[e] += xv * sg[e * DMODEL + k];
    }
    #pragma unroll
    for (int e = 0; e < NEXP; e++)
        #pragma unroll
        for (int o = 16; o; o >>= 1) acc[e] += __shfl_xor_sync(0xffffffffu, acc[e], o);
    if (lane == 0) {
        float m = acc[0];
        #pragma unroll
        for (int e = 1; e < NEXP; e++) m = fmaxf(m, acc[e]);
        float g[NEXP];
        #pragma unroll
        for (int e = 0; e < NEXP; e++) g[e] = __expf(acc[e] - m);
        int i0 = 0;
        #pragma unroll
        for (int e = 1; e < NEXP; e++) if (g[e] > g[i0]) i0 = e;
        int i1 = (i0 == 0) ? 1 : 0;
        #pragma unroll
        for (int e = 0; e < NEXP; e++) if (e != i0 && g[e] > g[i1]) i1 = e;
        float inv = 1.f / (g[i0] + g[i1]);
        te[t * 2] = i0; te[t * 2 + 1] = i1;
        tv[t * 2] = g[i0] * inv; tv[t * 2 + 1] = g[i1] * inv;
    }
}

// ---------------- routing ----------------
__global__ void route_zero(int* cnt, int* cur)
{
    if (threadIdx.x < NEXP) { cnt[threadIdx.x] = 0; cur[threadIdx.x] = 0; }
}
__global__ void route_count(const int* __restrict__ te, int* cnt)
{
    int t = blockIdx.x * 256 + threadIdx.x;
    atomicAdd(&cnt[te[t * 2]], 1);
    atomicAdd(&cnt[te[t * 2 + 1]], 1);
}
__global__ void route_offsets(const int* __restrict__ cnt, int* off)
{
    int s = 0;
    for (int e = 0; e < NEXP; e++) { off[e] = s; s += cnt[e]; }
    off[NEXP] = s;
}
__global__ void route_scatter(const int* __restrict__ te, const float* __restrict__ tv,
                              const int* __restrict__ off, int* cur,
                              int* ptok, float* pw, int* tok_pair)
{
    int t = blockIdx.x * 256 + threadIdx.x;
    #pragma unroll
    for (int k = 0; k < 2; k++) {
        int e = te[t * 2 + k];
        int pos = atomicAdd(&cur[e], 1);
        int p = off[e] + pos;
        ptok[p] = t;
        pw[p] = tv[t * 2 + k];
        tok_pair[t * 2 + k] = p;
    }
}

// ---------------- final combine ----------------
__global__ void moe_combine(const float* __restrict__ x, const float* __restrict__ y2,
                            const int* __restrict__ tok_pair, const float* __restrict__ pw,
                            float* __restrict__ out)
{
    int i = blockIdx.x * 256 + threadIdx.x;
    int t = i >> 10, n = i & (DMODEL - 1);
    int p0 = tok_pair[t * 2], p1 = tok_pair[t * 2 + 1];
    out[i] = x[i] + pw[p0] * y2[(size_t)p0 * DMODEL + n]
                  + pw[p1] * y2[(size_t)p1 * DMODEL + n];
}

// ---------------- launch ----------------
extern "C" void kernel_launch(void* const* d_in, const int* in_sizes, int n_in,
                              void* d_out, int out_size)
{
    (void)in_sizes; (void)n_in; (void)out_size;
    const float* x          = (const float*)d_in[0];
    const float* in_proj_w  = (const float*)d_in[1];
    const float* conv_w     = (const float*)d_in[2];
    const float* conv_b     = (const float*)d_in[3];
    const float* x_proj_w   = (const float*)d_in[4];
    const float* dt_proj_w  = (const float*)d_in[5];
    const float* dt_proj_b  = (const float*)d_in[6];
    const float* A_log      = (const float*)d_in[7];
    const float* Dvec       = (const float*)d_in[8];
    const float* out_proj_w = (const float*)d_in[9];
    const float* gate_w     = (const float*)d_in[10];
    const float* w1         = (const float*)d_in[11];
    const float* w2         = (const float*)d_in[12];
    float* out = (float*)d_out;

    float *p_xn, *p_xr, *p_u, *p_xdbl, *p_xp, *p_delta, *p_xm2, *p_xm2n, *p_y2, *p_tv, *p_pw;
    int *p_te, *p_cnt, *p_cur, *p_off, *p_ptok, *p_tp;
    cudaGetSymbolAddress((void**)&p_xn, g_xn);
    cudaGetSymbolAddress((void**)&p_xr, g_xr);
    cudaGetSymbolAddress((void**)&p_u, g_u);
    cudaGetSymbolAddress((void**)&p_xdbl, g_xdbl);
    cudaGetSymbolAddress((void**)&p_xp, g_xp);
    cudaGetSymbolAddress((void**)&p_delta, g_delta);
    cudaGetSymbolAddress((void**)&p_xm2, g_xm2);
    cudaGetSymbolAddress((void**)&p_xm2n, g_xm2n);
    cudaGetSymbolAddress((void**)&p_y2, g_y2);
    cudaGetSymbolAddress((void**)&p_te, g_top_e);
    cudaGetSymbolAddress((void**)&p_tv, g_top_v);
    cudaGetSymbolAddress((void**)&p_cnt, g_cnt);
    cudaGetSymbolAddress((void**)&p_cur, g_cur);
    cudaGetSymbolAddress((void**)&p_off, g_off);
    cudaGetSymbolAddress((void**)&p_ptok, g_ptok);
    cudaGetSymbolAddress((void**)&p_pw, g_pw);
    cudaGetSymbolAddress((void**)&p_tp, g_tok_pair);

    __half *xnh, *xdh, *yh, *x2h, *hh, *wih, *wdh, *woh, *w1h, *w2h;
    cudaGetSymbolAddress((void**)&xnh, h_xn);
    cudaGetSymbolAddress((void**)&xdh, h_xd);
    cudaGetSymbolAddress((void**)&yh,  h_y);
    cudaGetSymbolAddress((void**)&x2h, h_x2);
    cudaGetSymbolAddress((void**)&hh,  h_h);
    cudaGetSymbolAddress((void**)&wih, h_wi);
    cudaGetSymbolAddress((void**)&wdh, h_wd);
    cudaGetSymbolAddress((void**)&woh, h_wo);
    cudaGetSymbolAddress((void**)&w1h, h_w1);
    cudaGetSymbolAddress((void**)&w2h, h_w2);

    const int SMEM = NSTG * STG_B;   // 48 KB
    cudaFuncSetAttribute(hgemm<0, 0>, cudaFuncAttributeMaxDynamicSharedMemorySize, SMEM);
    cudaFuncSetAttribute(hgemm<2, 0>, cudaFuncAttributeMaxDynamicSharedMemorySize, SMEM);
    cudaFuncSetAttribute(hgemm<3, 0>, cudaFuncAttributeMaxDynamicSharedMemorySize, SMEM);
    cudaFuncSetAttribute(hgemm<1, 1>, cudaFuncAttributeMaxDynamicSharedMemorySize, SMEM);
    cudaFuncSetAttribute(hgemm<0, 2>, cudaFuncAttributeMaxDynamicSharedMemorySize, SMEM);

    // 0. convert weights to fp16
    conv_h<<<(2 * DINNER * DMODEL / 4 + 255) / 256, 256>>>((const float4*)in_proj_w, (uint2*)wih, 2 * DINNER * DMODEL / 4);
    conv_h<<<(DINNER * DTRANK / 4 + 255) / 256, 256>>>((const float4*)dt_proj_w, (uint2*)wdh, DINNER * DTRANK / 4);
    conv_h<<<(DMODEL * DINNER / 4 + 255) / 256, 256>>>((const float4*)out_proj_w, (uint2*)woh, DMODEL * DINNER / 4);
    conv_h<<<(int)((size_t)NEXP * HIDDEN * DMODEL / 4 + 255) / 256, 256>>>((const float4*)w1, (uint2*)w1h, NEXP * HIDDEN * DMODEL / 4);
    conv_h<<<(int)((size_t)NEXP * DMODEL * HIDDEN / 4 + 255) / 256, 256>>>((const float4*)w2, (uint2*)w2h, NEXP * DMODEL * HIDDEN / 4);

    // 1. xn = rmsnorm(x)
    rmsnorm_h<<<LSEQ, 256>>>(x, p_xn, xnh);
    // 2. xr = xn @ in_proj^T (2048x4096, K=1024)
    hgemm<0, 0><<<dim3(16, 32), 256, SMEM>>>(xnh, DMODEL, wih, DMODEL,
                                             p_xr, 2 * DINNER, LSEQ, 2 * DINNER,
                                             nullptr, nullptr, 0, nullptr, nullptr, nullptr);
    // 3. conv + silu
    conv_silu<<<(LSEQ * DINNER) / 256, 256>>>(p_xr, conv_w, conv_b, p_u);
    // 4. x_dbl = u @ x_proj^T (2048x96, K=2048) split-K exact fp32
    gemm_sk<<<dim3(32, 2, SPLITK), 256>>>(p_u, DINNER, x_proj_w, DINNER,
                                          p_xp, XDBL, LSEQ, XDBL, DINNER / SPLITK);
    reduce_sk<<<(LSEQ * XDBL + 255) / 256, 256>>>(p_xp, p_xdbl, xdh, LSEQ * XDBL);
    // 5. delta = softplus(dt @ dt_proj^T + b) (2048x2048, K=64)
    hgemm<3, 0><<<dim3(16, 16), 256, SMEM>>>(xdh, XDBL, wdh, DTRANK,
                                             p_delta, DINNER, LSEQ, DINNER,
                                             dt_proj_b, nullptr, 0, nullptr, nullptr, nullptr);
    // 6. selective scan -> y fp16
    scan_kernel<<<DINNER / 8, 128>>>(p_delta, p_u, p_xdbl, A_log, Dvec, p_xr, yh);
    // 7. xm2 = y @ out_proj^T + xn (2048x1024, K=2048)
    hgemm<2, 0><<<dim3(16, 8), 256, SMEM>>>(yh, DINNER, woh, DINNER,
                                            p_xm2, DMODEL, LSEQ, DMODEL,
                                            nullptr, p_xn, DMODEL, nullptr, nullptr, nullptr);
    // 8. xm2n = rmsnorm(xm2)
    rmsnorm_h<<<LSEQ, 256>>>(p_xm2, p_xm2n, x2h);
    // 9. gating + routing
    gate_topk<<<LSEQ / 4, 128>>>(p_xm2n, gate_w, p_te, p_tv);
    route_zero<<<1, 32>>>(p_cnt, p_cur);
    route_count<<<LSEQ / 256, 256>>>(p_te, p_cnt);
    route_offsets<<<1, 1>>>(p_cnt, p_off);
    route_scatter<<<LSEQ / 256, 256>>>(p_te, p_tv, p_off, p_cur, p_ptok, p_pw, p_tp);
    // 10. expert GEMMs
    hgemm<1, 1><<<dim3(32, 32, NEXP), 256, SMEM>>>(x2h, DMODEL, w1h, DMODEL,
                                                   nullptr, HIDDEN, 0, HIDDEN,
                                                   nullptr, nullptr, 0, p_off, p_ptok, hh);
    hgemm<0, 2><<<dim3(32, 8, NEXP), 256, SMEM>>>(hh, HIDDEN, w2h, HIDDEN,
                                                  p_y2, DMODEL, 0, DMODEL,
                                                  nullptr, nullptr, 0, p_off, nullptr, nullptr);
    moe_combine<<<(LSEQ * DMODEL) / 256, 256>>>(x, p_y2, p_tp, p_pw, out);
}